// round 7
// baseline (speedup 1.0000x reference)
#include <cuda_runtime.h>
#include <cuda_fp16.h>
#include <math.h>

// Fixed problem shapes
#define FCN   16
#define WT    593          // (FC+2)*FC + FC + FC*FC + FC + FC + 1
#define H_    152
#define W_    272
#define HW_   41344
#define B_    4
#define M_    32
#define BM_   128
#define EPS_  1.0e-4f

#define THREADS 128
#define PXPT    8                       // pixels per thread per iteration
#define PIXB    2048                    // pixels per block (2 iters of 1024)
#define NTILES  ((HW_ + PIXB - 1) / PIXB)   // 21

// Scratch (allocations forbidden): accumulators + fp16 feature buffer.
__device__ double g_neg_acc;
__device__ double g_pos_acc;
__device__ __align__(16) __half g_featH[B_ * FCN * HW_];   // 5.3 MB

__global__ void zero_acc_kernel() {
    g_neg_acc = 0.0;
    g_pos_acc = 0.0;
}

// Pre-pass: fp32 -> fp16 feature conversion (same rn rounding as before).
#define FEAT_N (B_ * FCN * HW_)
__global__ __launch_bounds__(256)
void feat_half_kernel(const float* __restrict__ sf) {
    const int i = (blockIdx.x * 256 + threadIdx.x) * 8;
    if (i + 8 <= FEAT_N) {
        const float4 a = *(const float4*)(sf + i);
        const float4 b = *(const float4*)(sf + i + 4);
        __half2 h0 = __floats2half2_rn(a.x, a.y);
        __half2 h1 = __floats2half2_rn(a.z, a.w);
        __half2 h2 = __floats2half2_rn(b.x, b.y);
        __half2 h3 = __floats2half2_rn(b.z, b.w);
        uint4 o;
        o.x = *(unsigned*)&h0; o.y = *(unsigned*)&h1;
        o.z = *(unsigned*)&h2; o.w = *(unsigned*)&h3;
        *(uint4*)(g_featH + i) = o;
    }
}

// load an 8-byte-aligned pair of dup half2 weights (i must be even)
__device__ __forceinline__ void ldpair(const __half2* __restrict__ swh, int i,
                                       __half2& w0, __half2& w1) {
    const uint2 v = *(const uint2*)&swh[i];
    w0 = *reinterpret_cast<const __half2*>(&v.x);
    w1 = *reinterpret_cast<const __half2*>(&v.y);
}
__device__ __forceinline__ __half2 asH2(unsigned u) {
    return *reinterpret_cast<const __half2*>(&u);
}

// Shared layout (half2 dup: swh[i] = (w_i, w_i)):
//   [0,288) w1[o*18+c] ; [288,304) b1 ; [304,560) w2[o*16+c] ; [560,576) b2 ;
//   [576,592) w3 ; [592] b3
__global__ __launch_bounds__(THREADS, 3)
void sch_loss_main(const float* __restrict__ conv_weight,
                   const float* __restrict__ mask,
                   const int*   __restrict__ pre_ind,
                   const float* __restrict__ target,
                   const int*   __restrict__ ind)
{
    __shared__ __align__(16) __half2 swh[WT + 1];
    __shared__ float sred[THREADS / 32];

    const int bm  = blockIdx.y;        // b*32 + m
    const int b   = bm >> 5;
    const int tid = threadIdx.x;
    const int pi  = pre_ind[bm];

    // Gather 593-float weight vector (strided), convert to duplicated half2.
    for (int c = tid; c < WT; c += THREADS) {
        const float v = conv_weight[((long long)b * WT + c) * HW_ + pi];
        swh[c] = __floats2half2_rn(v, v);
    }
    __syncthreads();

    const __half* __restrict__ sfh = g_featH + (long long)b * FCN * HW_;
    const float*  __restrict__ tg  = target  + (long long)bm * HW_;
    const int   posind = ind[bm];
    const float mval   = mask[bm];

    const float x0 = (float)(pi % W_);
    const float y0 = (float)pi / (float)W_;     // float division, matching reference
    const float inv128 = 1.0f / 128.0f;

    const int base  = blockIdx.x * PIXB;
    const int limit = (base + PIXB < HW_) ? (base + PIXB) : HW_;  // multiple of 8

    float negAcc = 0.0f;
    const __half2 h2zero = __floats2half2_rn(0.0f, 0.0f);

    for (int p = base + PXPT * tid; p < limit; p += PXPT * THREADS) {
        // 272 % 8 == 0: the 8-pixel group never wraps a row
        const int   px = p % W_;
        const float yr = ((float)(p / W_) - y0) * inv128;
        const float xr0 = ((float)px - x0) * inv128;
        const __half2 xrA = __floats2half2_rn(xr0,                  xr0 +        inv128);
        const __half2 xrB = __floats2half2_rn(xr0 + 2.0f * inv128,  xr0 + 3.0f * inv128);
        const __half2 xrC = __floats2half2_rn(xr0 + 4.0f * inv128,  xr0 + 5.0f * inv128);
        const __half2 xrD = __floats2half2_rn(xr0 + 6.0f * inv128,  xr0 + 7.0f * inv128);
        const __half2 yrP = __floats2half2_rn(yr, yr);

        // prefetch targets early (overlap with MLP)
        const float4 t4a = *(const float4*)(tg + p);
        const float4 t4b = *(const float4*)(tg + p + 4);

        // ---- layer 1 (18 -> 16) over 4 pixel-pairs A..D ----
        __half2 hA[FCN], hB[FCN], hC[FCN], hD[FCN];
        #pragma unroll
        for (int o = 0; o < FCN; o += 2) {
            __half2 b0, b1x;
            ldpair(swh, 288 + o, b0, b1x);
            hA[o] = b0;  hB[o] = b0;  hC[o] = b0;  hD[o] = b0;
            hA[o+1] = b1x; hB[o+1] = b1x; hC[o+1] = b1x; hD[o+1] = b1x;
        }

        // two batches of 8 channels: one LDG.128 of fp16 per channel covers all 8 px
        #pragma unroll
        for (int half = 0; half < 2; ++half) {
            const int c0 = half * 8;
            __half2 fA[8], fB[8], fC[8], fD[8];
            #pragma unroll
            for (int c = 0; c < 8; ++c) {
                const uint4 v = *(const uint4*)(sfh + (long long)(c0 + c) * HW_ + p);
                fA[c] = asH2(v.x); fB[c] = asH2(v.y);
                fC[c] = asH2(v.z); fD[c] = asH2(v.w);
            }
            #pragma unroll
            for (int o = 0; o < FCN; ++o) {
                const int wb = o * 18 + c0;          // even -> aligned pairs
                __half2 aA = hA[o], aB = hB[o], aC = hC[o], aD = hD[o];
                #pragma unroll
                for (int c = 0; c < 8; c += 2) {
                    __half2 w0, w1;
                    ldpair(swh, wb + c, w0, w1);
                    aA = __hfma2(w0, fA[c], aA);
                    aB = __hfma2(w0, fB[c], aB);
                    aC = __hfma2(w0, fC[c], aC);
                    aD = __hfma2(w0, fD[c], aD);
                    aA = __hfma2(w1, fA[c+1], aA);
                    aB = __hfma2(w1, fB[c+1], aB);
                    aC = __hfma2(w1, fC[c+1], aC);
                    aD = __hfma2(w1, fD[c+1], aD);
                }
                hA[o] = aA; hB[o] = aB; hC[o] = aC; hD[o] = aD;
            }
        }

        // coordinate channels (c = 16,17 -> aligned pair) + relu
        #pragma unroll
        for (int o = 0; o < FCN; ++o) {
            __half2 wx, wy;
            ldpair(swh, o * 18 + 16, wx, wy);
            __half2 aA = hA[o], aB = hB[o], aC = hC[o], aD = hD[o];
            aA = __hfma2(wx, xrA, aA); aA = __hfma2(wy, yrP, aA);
            aB = __hfma2(wx, xrB, aB); aB = __hfma2(wy, yrP, aB);
            aC = __hfma2(wx, xrC, aC); aC = __hfma2(wy, yrP, aC);
            aD = __hfma2(wx, xrD, aD); aD = __hfma2(wy, yrP, aD);
            hA[o] = __hmax2(aA, h2zero);
            hB[o] = __hmax2(aB, h2zero);
            hC[o] = __hmax2(aC, h2zero);
            hD[o] = __hmax2(aD, h2zero);
        }

        // ---- layer 2 (16 -> 16) fused with layer 3 (16 -> 1), one o at a time ----
        __half2 zA = swh[592], zB = zA, zC = zA, zD = zA;
        #pragma unroll
        for (int o = 0; o < FCN; o += 2) {
            __half2 b20, b21;
            ldpair(swh, 560 + o, b20, b21);
            __half2 w30, w31;
            ldpair(swh, 576 + o, w30, w31);

            // o
            {
                __half2 aA = b20, aB = b20, aC = b20, aD = b20;
                const int wb = 304 + o * 16;
                #pragma unroll
                for (int c = 0; c < FCN; c += 2) {
                    __half2 w0, w1;
                    ldpair(swh, wb + c, w0, w1);
                    aA = __hfma2(w0, hA[c], aA);
                    aB = __hfma2(w0, hB[c], aB);
                    aC = __hfma2(w0, hC[c], aC);
                    aD = __hfma2(w0, hD[c], aD);
                    aA = __hfma2(w1, hA[c+1], aA);
                    aB = __hfma2(w1, hB[c+1], aB);
                    aC = __hfma2(w1, hC[c+1], aC);
                    aD = __hfma2(w1, hD[c+1], aD);
                }
                zA = __hfma2(w30, __hmax2(aA, h2zero), zA);
                zB = __hfma2(w30, __hmax2(aB, h2zero), zB);
                zC = __hfma2(w30, __hmax2(aC, h2zero), zC);
                zD = __hfma2(w30, __hmax2(aD, h2zero), zD);
            }
            // o + 1
            {
                __half2 aA = b21, aB = b21, aC = b21, aD = b21;
                const int wb = 304 + (o + 1) * 16;
                #pragma unroll
                for (int c = 0; c < FCN; c += 2) {
                    __half2 w0, w1;
                    ldpair(swh, wb + c, w0, w1);
                    aA = __hfma2(w0, hA[c], aA);
                    aB = __hfma2(w0, hB[c], aB);
                    aC = __hfma2(w0, hC[c], aC);
                    aD = __hfma2(w0, hD[c], aD);
                    aA = __hfma2(w1, hA[c+1], aA);
                    aB = __hfma2(w1, hB[c+1], aB);
                    aC = __hfma2(w1, hC[c+1], aC);
                    aD = __hfma2(w1, hD[c+1], aD);
                }
                zA = __hfma2(w31, __hmax2(aA, h2zero), zA);
                zB = __hfma2(w31, __hmax2(aB, h2zero), zB);
                zC = __hfma2(w31, __hmax2(aC, h2zero), zC);
                zD = __hfma2(w31, __hmax2(aD, h2zero), zD);
            }
        }

        // ---- epilogue (fp32): sigmoid + clip + focal terms for 8 px ----
        const float2 zAf = __half22float2(zA);
        const float2 zBf = __half22float2(zB);
        const float2 zCf = __half22float2(zC);
        const float2 zDf = __half22float2(zD);
        const float z[8]  = {zAf.x, zAf.y, zBf.x, zBf.y, zCf.x, zCf.y, zDf.x, zDf.y};
        const float tt[8] = {t4a.x, t4a.y, t4a.z, t4a.w, t4b.x, t4b.y, t4b.z, t4b.w};

        #pragma unroll
        for (int i = 0; i < 8; ++i) {
            float hm = 1.0f / (1.0f + __expf(-z[i]));
            hm = fminf(fmaxf(hm, EPS_), 1.0f - EPS_);
            float q = 1.0f - tt[i];
            q = q * q; q = q * q;                       // (1-t)^4
            negAcc += __logf(1.0f - hm) * hm * hm * q;
            if (p + i == posind) {
                const float om = 1.0f - hm;
                atomicAdd(&g_pos_acc, (double)(__logf(hm) * om * om * mval));
            }
        }
    }

    // ---- block reduction, one double atomic per block ----
    #pragma unroll
    for (int off = 16; off > 0; off >>= 1)
        negAcc += __shfl_down_sync(0xFFFFFFFFu, negAcc, off);
    if ((tid & 31) == 0) sred[tid >> 5] = negAcc;
    __syncthreads();
    if (tid < 32) {
        float v = (tid < THREADS / 32) ? sred[tid] : 0.0f;
        #pragma unroll
        for (int off = 2; off > 0; off >>= 1)
            v += __shfl_down_sync(0xFFFFFFFFu, v, off);
        if (tid == 0) atomicAdd(&g_neg_acc, (double)v);
    }
}

__global__ void finalize_kernel(const float* __restrict__ mask, float* __restrict__ out)
{
    if (threadIdx.x == 0) {
        float np = 0.0f;
        for (int i = 0; i < BM_; ++i) np += mask[i];
        const double neg = g_neg_acc;
        const double pos = g_pos_acc;
        double loss;
        if (np == 0.0f) loss = -neg;
        else            loss = -(pos + neg) / (double)fmaxf(np, 1.0f);
        out[0] = (float)loss;
    }
}

extern "C" void kernel_launch(void* const* d_in, const int* in_sizes, int n_in,
                              void* d_out, int out_size)
{
    const float* sch_feat    = (const float*)d_in[0];
    const float* conv_weight = (const float*)d_in[1];
    const float* mask        = (const float*)d_in[2];
    const int*   pre_ind     = (const int*)  d_in[3];
    const float* target      = (const float*)d_in[4];
    const int*   ind         = (const int*)  d_in[5];
    float* out = (float*)d_out;

    zero_acc_kernel<<<1, 1>>>();
    feat_half_kernel<<<(FEAT_N / 8 + 255) / 256, 256>>>(sch_feat);

    dim3 grid(NTILES, BM_);
    sch_loss_main<<<grid, THREADS>>>(conv_weight, mask, pre_ind, target, ind);

    finalize_kernel<<<1, 32>>>(mask, out);
}

// round 8
// speedup vs baseline: 1.3648x; 1.3648x over previous
#include <cuda_runtime.h>
#include <cuda_fp16.h>
#include <math.h>

// Fixed problem shapes
#define FCN   16
#define WT    593
#define H_    152
#define W_    272
#define HW_   41344
#define B_    4
#define M_    32
#define BM_   128
#define EPS_  1.0e-4f
#define NT16  2584            // HW_/16 pixel tiles
#define GRIDX 20              // main kernel blocks along tiles

// Scratch (allocations forbidden)
__device__ double g_neg_acc;
__device__ double g_pos_acc;
__device__ uint4  g_featX[(long long)B_ * NT16 * 32];   // fragment-ordered features, 5.3MB

__global__ void zero_acc_kernel() {
    g_neg_acc = 0.0;
    g_pos_acc = 0.0;
}

__device__ __forceinline__ unsigned pack_h2(float lo, float hi) {
    unsigned d;
    asm("cvt.rn.f16x2.f32 %0, %1, %2;" : "=r"(d) : "f"(hi), "f"(lo));  // %1->upper, %2->lower
    return d;
}

// ---- pre-pass: build m16k16 A fragments for all 16px tiles ----
// A frag layout (m16n8k16, row-major A): lane g=l>>2, t=l&3;
//  a0=(px g,  c 2t|2t+1)  a1=(px g+8, c 2t|2t+1)  a2=(px g, c 2t+8|2t+9)  a3=(px g+8, ...)
__global__ __launch_bounds__(32)
void feat_frag_kernel(const float* __restrict__ sf) {
    __shared__ float sm[16][16];   // [c][px]
    const int tile = blockIdx.x;
    const int b    = blockIdx.y;
    const int t    = threadIdx.x;
    const int base = tile * 16;

    const int c  = t >> 1;
    const int h8 = (t & 1) * 8;
    const float* src = sf + ((long long)b * FCN + c) * HW_ + base + h8;
    const float4 v0 = *(const float4*)src;
    const float4 v1 = *(const float4*)(src + 4);
    sm[c][h8 + 0] = v0.x; sm[c][h8 + 1] = v0.y; sm[c][h8 + 2] = v0.z; sm[c][h8 + 3] = v0.w;
    sm[c][h8 + 4] = v1.x; sm[c][h8 + 5] = v1.y; sm[c][h8 + 6] = v1.z; sm[c][h8 + 7] = v1.w;
    __syncwarp();

    const int g  = t >> 2;
    const int tq = t & 3;
    const int k0 = 2 * tq, k1 = k0 + 1, k2 = k0 + 8, k3 = k2 + 1;

    __half2 a0 = __floats2half2_rn(sm[k0][g],     sm[k1][g]);
    __half2 a1 = __floats2half2_rn(sm[k0][g + 8], sm[k1][g + 8]);
    __half2 a2 = __floats2half2_rn(sm[k2][g],     sm[k3][g]);
    __half2 a3 = __floats2half2_rn(sm[k2][g + 8], sm[k3][g + 8]);

    uint4 o;
    o.x = *(unsigned*)&a0; o.y = *(unsigned*)&a1;
    o.z = *(unsigned*)&a2; o.w = *(unsigned*)&a3;
    g_featX[((long long)b * NT16 + tile) * 32 + t] = o;
}

__device__ __forceinline__ void mma16816(
    float& d0, float& d1, float& d2, float& d3,
    unsigned a0, unsigned a1, unsigned a2, unsigned a3,
    unsigned b0, unsigned b1,
    float c0, float c1, float c2, float c3)
{
    asm("mma.sync.aligned.m16n8k16.row.col.f32.f16.f16.f32 "
        "{%0,%1,%2,%3}, {%4,%5,%6,%7}, {%8,%9}, {%10,%11,%12,%13};"
        : "=f"(d0), "=f"(d1), "=f"(d2), "=f"(d3)
        : "r"(a0), "r"(a1), "r"(a2), "r"(a3), "r"(b0), "r"(b1),
          "f"(c0), "f"(c1), "f"(c2), "f"(c3));
}

__global__ __launch_bounds__(128, 4)
void sch_loss_main(const float* __restrict__ conv_weight,
                   const float* __restrict__ mask,
                   const int*   __restrict__ pre_ind,
                   const float* __restrict__ target,
                   const int*   __restrict__ ind)
{
    // weights: fp16 matrices for mma B, fp32 vectors for bias/coords/head
    __shared__ __align__(4) __half w1h[256];   // [o*16 + c], c<16
    __shared__ __align__(4) __half w2h[256];   // [o*16 + c]
    __shared__ float b1f[16], b2f[16], w3f[16], wxf[16], wyf[16];
    __shared__ float b3s;
    __shared__ float sred[4];

    const int bm   = blockIdx.y;
    const int b    = bm >> 5;
    const int tid  = threadIdx.x;
    const int wid  = tid >> 5;
    const int lane = tid & 31;
    const int pi   = pre_ind[bm];

    // ---- prologue: gather + route 593 weights ----
    for (int idx = tid; idx < WT; idx += 128) {
        const float v = conv_weight[((long long)b * WT + idx) * HW_ + pi];
        if (idx < 288) {
            const int o = idx / 18, c = idx % 18;
            if      (c < 16)  w1h[o * 16 + c] = __float2half_rn(v);
            else if (c == 16) wxf[o] = v;
            else              wyf[o] = v;
        } else if (idx < 304) b1f[idx - 288] = v;
        else if (idx < 560)   w2h[idx - 304] = __float2half_rn(v);
        else if (idx < 576)   b2f[idx - 560] = v;
        else if (idx < 592)   w3f[idx - 576] = v;
        else                  b3s = v;
    }
    __syncthreads();

    // ---- per-thread register fragments (fixed for whole block) ----
    const int g  = lane >> 2;
    const int tq = lane & 3;
    const int k0 = 2 * tq, k1 = k0 + 1, k2 = k0 + 8, k3 = k2 + 1;

    // B frags (col-major k16n8): b_reg0 = (k=2t, n), (k=2t+1, n); b_reg1 = k+8
    const unsigned b1a0 = *(const unsigned*)&w1h[g * 16 + k0];
    const unsigned b1a1 = *(const unsigned*)&w1h[g * 16 + k2];
    const unsigned b1b0 = *(const unsigned*)&w1h[(g + 8) * 16 + k0];
    const unsigned b1b1 = *(const unsigned*)&w1h[(g + 8) * 16 + k2];
    const unsigned b2a0 = *(const unsigned*)&w2h[g * 16 + k0];
    const unsigned b2a1 = *(const unsigned*)&w2h[g * 16 + k2];
    const unsigned b2b0 = *(const unsigned*)&w2h[(g + 8) * 16 + k0];
    const unsigned b2b1 = *(const unsigned*)&w2h[(g + 8) * 16 + k2];

    // fp32 per-column constants at this thread's D columns {k0,k1,k2,k3}
    const float bb10 = b1f[k0], bb11 = b1f[k1], bb12 = b1f[k2], bb13 = b1f[k3];
    const float bb20 = b2f[k0], bb21 = b2f[k1], bb22 = b2f[k2], bb23 = b2f[k3];
    const float wx0 = wxf[k0], wx1 = wxf[k1], wx2 = wxf[k2], wx3 = wxf[k3];
    const float wy0 = wyf[k0], wy1 = wyf[k1], wy2 = wyf[k2], wy3 = wyf[k3];
    const float w30 = w3f[k0], w31 = w3f[k1], w32 = w3f[k2], w33 = w3f[k3];
    const float b3v = b3s;

    const float* __restrict__ tg = target + (long long)bm * HW_;
    const uint4* __restrict__ fx = g_featX + (long long)b * NT16 * 32;
    const int   posind = ind[bm];
    const float mval   = mask[bm];

    const float x0 = (float)(pi % W_);
    const float y0 = (float)pi / (float)W_;     // float division, matching reference
    const float inv128 = 1.0f / 128.0f;

    float negAcc = 0.0f;

    for (int tile = blockIdx.x * 4 + wid; tile < NT16; tile += GRIDX * 4) {
        const uint4 af = fx[(long long)tile * 32 + lane];

        // coords: a 16px tile never wraps a row (272 = 17*16)
        const float xr0 = ((float)((tile % 17) * 16 + g) - x0) * inv128;
        const float xr1 = xr0 + 8.0f * inv128;
        const float yrv = ((float)(tile / 17) - y0) * inv128;

        // layer1: C = b1 + yr*wy ; post-mma add xr*wx ; relu ; pack to layer2 A
        const float cy0 = fmaf(yrv, wy0, bb10);
        const float cy1 = fmaf(yrv, wy1, bb11);
        const float cy2 = fmaf(yrv, wy2, bb12);
        const float cy3 = fmaf(yrv, wy3, bb13);

        float d0, d1, d2, d3, e0, e1, e2, e3;
        mma16816(d0, d1, d2, d3, af.x, af.y, af.z, af.w, b1a0, b1a1, cy0, cy1, cy0, cy1);
        mma16816(e0, e1, e2, e3, af.x, af.y, af.z, af.w, b1b0, b1b1, cy2, cy3, cy2, cy3);
        d0 = fmaf(xr0, wx0, d0); d1 = fmaf(xr0, wx1, d1);
        d2 = fmaf(xr1, wx0, d2); d3 = fmaf(xr1, wx1, d3);
        e0 = fmaf(xr0, wx2, e0); e1 = fmaf(xr0, wx3, e1);
        e2 = fmaf(xr1, wx2, e2); e3 = fmaf(xr1, wx3, e3);

        // D -> A chaining: A2 = pack(relu(D))
        const unsigned A0 = pack_h2(fmaxf(d0, 0.0f), fmaxf(d1, 0.0f));
        const unsigned A1 = pack_h2(fmaxf(d2, 0.0f), fmaxf(d3, 0.0f));
        const unsigned A2 = pack_h2(fmaxf(e0, 0.0f), fmaxf(e1, 0.0f));
        const unsigned A3 = pack_h2(fmaxf(e2, 0.0f), fmaxf(e3, 0.0f));

        // layer2 (C = b2), relu, then layer3 dot with w3
        mma16816(d0, d1, d2, d3, A0, A1, A2, A3, b2a0, b2a1, bb20, bb21, bb20, bb21);
        mma16816(e0, e1, e2, e3, A0, A1, A2, A3, b2b0, b2b1, bb22, bb23, bb22, bb23);
        d0 = fmaxf(d0, 0.0f); d1 = fmaxf(d1, 0.0f);
        d2 = fmaxf(d2, 0.0f); d3 = fmaxf(d3, 0.0f);
        e0 = fmaxf(e0, 0.0f); e1 = fmaxf(e1, 0.0f);
        e2 = fmaxf(e2, 0.0f); e3 = fmaxf(e3, 0.0f);

        float zr0 = d0 * w30; zr0 = fmaf(d1, w31, zr0);
        zr0 = fmaf(e0, w32, zr0); zr0 = fmaf(e1, w33, zr0);   // px = base+g
        float zr1 = d2 * w30; zr1 = fmaf(d3, w31, zr1);
        zr1 = fmaf(e2, w32, zr1); zr1 = fmaf(e3, w33, zr1);   // px = base+g+8

        // quad reduce over the 4 column-threads (lanes 4g..4g+3)
        zr0 += __shfl_xor_sync(0xFFFFFFFFu, zr0, 1);
        zr0 += __shfl_xor_sync(0xFFFFFFFFu, zr0, 2);
        zr1 += __shfl_xor_sync(0xFFFFFFFFu, zr1, 1);
        zr1 += __shfl_xor_sync(0xFFFFFFFFu, zr1, 2);

        // distribute: lane L<16 takes z of pixel base+L
        const int src = (lane * 4) & 31;
        const float zlo = __shfl_sync(0xFFFFFFFFu, zr0, src);
        const float zhi = __shfl_sync(0xFFFFFFFFu, zr1, src);

        if (lane < 16) {
            const float zv = ((lane < 8) ? zlo : zhi) + b3v;
            const int   px = tile * 16 + lane;
            const float t  = tg[px];
            float hm = 1.0f / (1.0f + __expf(-zv));
            hm = fminf(fmaxf(hm, EPS_), 1.0f - EPS_);
            float q = 1.0f - t;
            q = q * q; q = q * q;
            negAcc += __logf(1.0f - hm) * hm * hm * q;
            if (px == posind) {
                const float om = 1.0f - hm;
                atomicAdd(&g_pos_acc, (double)(__logf(hm) * om * om * mval));
            }
        }
    }

    // ---- block reduction, one double atomic per block ----
    #pragma unroll
    for (int off = 16; off > 0; off >>= 1)
        negAcc += __shfl_down_sync(0xFFFFFFFFu, negAcc, off);
    if (lane == 0) sred[wid] = negAcc;
    __syncthreads();
    if (tid < 32) {
        float v = (tid < 4) ? sred[tid] : 0.0f;
        #pragma unroll
        for (int off = 2; off > 0; off >>= 1)
            v += __shfl_down_sync(0xFFFFFFFFu, v, off);
        if (tid == 0) atomicAdd(&g_neg_acc, (double)v);
    }
}

__global__ void finalize_kernel(const float* __restrict__ mask, float* __restrict__ out)
{
    if (threadIdx.x == 0) {
        float np = 0.0f;
        for (int i = 0; i < BM_; ++i) np += mask[i];
        const double neg = g_neg_acc;
        const double pos = g_pos_acc;
        double loss;
        if (np == 0.0f) loss = -neg;
        else            loss = -(pos + neg) / (double)fmaxf(np, 1.0f);
        out[0] = (float)loss;
    }
}

extern "C" void kernel_launch(void* const* d_in, const int* in_sizes, int n_in,
                              void* d_out, int out_size)
{
    const float* sch_feat    = (const float*)d_in[0];
    const float* conv_weight = (const float*)d_in[1];
    const float* mask        = (const float*)d_in[2];
    const int*   pre_ind     = (const int*)  d_in[3];
    const float* target      = (const float*)d_in[4];
    const int*   ind         = (const int*)  d_in[5];
    float* out = (float*)d_out;

    zero_acc_kernel<<<1, 1>>>();
    feat_frag_kernel<<<dim3(NT16, B_), 32>>>(sch_feat);

    dim3 grid(GRIDX, BM_);
    sch_loss_main<<<grid, 128>>>(conv_weight, mask, pre_ind, target, ind);

    finalize_kernel<<<1, 32>>>(mask, out);
}

// round 9
// speedup vs baseline: 1.7664x; 1.2943x over previous
#include <cuda_runtime.h>
#include <cuda_fp16.h>
#include <math.h>

// Fixed problem shapes
#define FCN   16
#define WT    593
#define H_    152
#define W_    272
#define HW_   41344
#define B_    4
#define M_    32
#define BM_   128
#define EPS_  1.0e-4f
#define NT16  2584            // HW_/16 pixel tiles
#define NPAIR 1292            // tile pairs
#define GRIDX 20
#define TOTALBLK (GRIDX * BM_)

// Scratch (allocations forbidden)
__device__ double   g_neg_acc;
__device__ double   g_pos_acc;
__device__ unsigned g_done;
__device__ uint4    g_featX[(long long)B_ * NT16 * 32];   // fragment-ordered features

__device__ __forceinline__ unsigned pack_h2(float lo, float hi) {
    unsigned d;
    asm("cvt.rn.f16x2.f32 %0, %1, %2;" : "=r"(d) : "f"(hi), "f"(lo));
    return d;
}

// ---- pre-pass: build m16k16 A fragments; also resets accumulators ----
__global__ __launch_bounds__(128)
void feat_frag_kernel(const float* __restrict__ sf) {
    if (blockIdx.x == 0 && blockIdx.y == 0 && threadIdx.x == 0) {
        g_neg_acc = 0.0;
        g_pos_acc = 0.0;
        g_done    = 0u;
    }
    __shared__ float sm[4][16][16];   // [w][c][px]
    const int w    = threadIdx.x >> 5;
    const int t    = threadIdx.x & 31;
    const int tile = blockIdx.x * 4 + w;
    const int b    = blockIdx.y;
    const int base = tile * 16;

    const int c  = t >> 1;
    const int h8 = (t & 1) * 8;
    const float* src = sf + ((long long)b * FCN + c) * HW_ + base + h8;
    const float4 v0 = *(const float4*)src;
    const float4 v1 = *(const float4*)(src + 4);
    sm[w][c][h8 + 0] = v0.x; sm[w][c][h8 + 1] = v0.y;
    sm[w][c][h8 + 2] = v0.z; sm[w][c][h8 + 3] = v0.w;
    sm[w][c][h8 + 4] = v1.x; sm[w][c][h8 + 5] = v1.y;
    sm[w][c][h8 + 6] = v1.z; sm[w][c][h8 + 7] = v1.w;
    __syncwarp();

    const int g  = t >> 2;
    const int tq = t & 3;
    const int k0 = 2 * tq, k1 = k0 + 1, k2 = k0 + 8, k3 = k2 + 1;

    __half2 a0 = __floats2half2_rn(sm[w][k0][g],     sm[w][k1][g]);
    __half2 a1 = __floats2half2_rn(sm[w][k0][g + 8], sm[w][k1][g + 8]);
    __half2 a2 = __floats2half2_rn(sm[w][k2][g],     sm[w][k3][g]);
    __half2 a3 = __floats2half2_rn(sm[w][k2][g + 8], sm[w][k3][g + 8]);

    uint4 o;
    o.x = *(unsigned*)&a0; o.y = *(unsigned*)&a1;
    o.z = *(unsigned*)&a2; o.w = *(unsigned*)&a3;
    g_featX[((long long)b * NT16 + tile) * 32 + t] = o;
}

__device__ __forceinline__ void mma16816(
    float& d0, float& d1, float& d2, float& d3,
    unsigned a0, unsigned a1, unsigned a2, unsigned a3,
    unsigned b0, unsigned b1,
    float c0, float c1, float c2, float c3)
{
    asm("mma.sync.aligned.m16n8k16.row.col.f32.f16.f16.f32 "
        "{%0,%1,%2,%3}, {%4,%5,%6,%7}, {%8,%9}, {%10,%11,%12,%13};"
        : "=f"(d0), "=f"(d1), "=f"(d2), "=f"(d3)
        : "r"(a0), "r"(a1), "r"(a2), "r"(a3), "r"(b0), "r"(b1),
          "f"(c0), "f"(c1), "f"(c2), "f"(c3));
}

__global__ __launch_bounds__(128, 4)
void sch_loss_main(const float* __restrict__ conv_weight,
                   const float* __restrict__ mask,
                   const int*   __restrict__ pre_ind,
                   const float* __restrict__ target,
                   const int*   __restrict__ ind,
                   float* __restrict__ out)
{
    __shared__ __align__(4) __half w1h[256];   // [o*16 + c], c<16
    __shared__ __align__(4) __half w2h[256];   // [o*16 + c]
    __shared__ float b1f[16], b2f[16], w3f[16], wxf[16], wyf[16];
    __shared__ float b3s;
    __shared__ float sred[4];
    __shared__ int   s_last;

    const int bm   = blockIdx.y;
    const int b    = bm >> 5;
    const int tid  = threadIdx.x;
    const int wid  = tid >> 5;
    const int lane = tid & 31;
    const int pi   = pre_ind[bm];

    // ---- prologue: gather + route 593 weights ----
    for (int idx = tid; idx < WT; idx += 128) {
        const float v = conv_weight[((long long)b * WT + idx) * HW_ + pi];
        if (idx < 288) {
            const int o = idx / 18, c = idx % 18;
            if      (c < 16)  w1h[o * 16 + c] = __float2half_rn(v);
            else if (c == 16) wxf[o] = v;
            else              wyf[o] = v;
        } else if (idx < 304) b1f[idx - 288] = v;
        else if (idx < 560)   w2h[idx - 304] = __float2half_rn(v);
        else if (idx < 576)   b2f[idx - 560] = v;
        else if (idx < 592)   w3f[idx - 576] = v;
        else                  b3s = v;
    }
    __syncthreads();

    const int g  = lane >> 2;
    const int tq = lane & 3;
    const int k0 = 2 * tq, k2 = k0 + 8;
    const int k1 = k0 + 1, k3 = k2 + 1;

    // B frags (col-major k16n8), fixed for the block
    const unsigned b1a0 = *(const unsigned*)&w1h[g * 16 + k0];
    const unsigned b1a1 = *(const unsigned*)&w1h[g * 16 + k2];
    const unsigned b1b0 = *(const unsigned*)&w1h[(g + 8) * 16 + k0];
    const unsigned b1b1 = *(const unsigned*)&w1h[(g + 8) * 16 + k2];
    const unsigned b2a0 = *(const unsigned*)&w2h[g * 16 + k0];
    const unsigned b2a1 = *(const unsigned*)&w2h[g * 16 + k2];
    const unsigned b2b0 = *(const unsigned*)&w2h[(g + 8) * 16 + k0];
    const unsigned b2b1 = *(const unsigned*)&w2h[(g + 8) * 16 + k2];

    const float bb10 = b1f[k0], bb11 = b1f[k1], bb12 = b1f[k2], bb13 = b1f[k3];
    const float bb20 = b2f[k0], bb21 = b2f[k1], bb22 = b2f[k2], bb23 = b2f[k3];
    const float wx0 = wxf[k0], wx1 = wxf[k1], wx2 = wxf[k2], wx3 = wxf[k3];
    const float wy0 = wyf[k0], wy1 = wyf[k1], wy2 = wyf[k2], wy3 = wyf[k3];
    const float w30 = w3f[k0], w31 = w3f[k1], w32 = w3f[k2], w33 = w3f[k3];
    const float b3v = b3s;

    const float* __restrict__ tg = target + (long long)bm * HW_;
    const uint4* __restrict__ fx = g_featX + (long long)b * NT16 * 32;
    const int   posind = ind[bm];
    const float mval   = mask[bm];

    const float x0 = (float)(pi % W_);
    const float y0 = (float)pi / (float)W_;     // float division, matching reference
    const float inv128 = 1.0f / 128.0f;

    float negAcc = 0.0f;

    for (int pp = blockIdx.x * 4 + wid; pp < NPAIR; pp += GRIDX * 4) {
        const int tile0 = pp * 2;

        // independent loads first (batched MLP=3)
        const uint4 afA = fx[(long long)tile0 * 32 + lane];
        const uint4 afB = fx[(long long)(tile0 + 1) * 32 + lane];
        const float tgv = tg[tile0 * 16 + lane];   // 32 contiguous px, coalesced

        float zr0[2], zr1[2];

        #pragma unroll
        for (int t = 0; t < 2; ++t) {
            const int  tile = tile0 + t;
            const uint4 af  = t ? afB : afA;

            const float xrl = ((float)((tile % 17) * 16 + g) - x0) * inv128;
            const float xrh = xrl + 8.0f * inv128;
            const float yrv = ((float)(tile / 17) - y0) * inv128;

            const float cy0 = fmaf(yrv, wy0, bb10);
            const float cy1 = fmaf(yrv, wy1, bb11);
            const float cy2 = fmaf(yrv, wy2, bb12);
            const float cy3 = fmaf(yrv, wy3, bb13);

            float d0, d1, d2, d3, e0, e1, e2, e3;
            mma16816(d0, d1, d2, d3, af.x, af.y, af.z, af.w, b1a0, b1a1, cy0, cy1, cy0, cy1);
            mma16816(e0, e1, e2, e3, af.x, af.y, af.z, af.w, b1b0, b1b1, cy2, cy3, cy2, cy3);
            d0 = fmaf(xrl, wx0, d0); d1 = fmaf(xrl, wx1, d1);
            d2 = fmaf(xrh, wx0, d2); d3 = fmaf(xrh, wx1, d3);
            e0 = fmaf(xrl, wx2, e0); e1 = fmaf(xrl, wx3, e1);
            e2 = fmaf(xrh, wx2, e2); e3 = fmaf(xrh, wx3, e3);

            const unsigned A0 = pack_h2(fmaxf(d0, 0.0f), fmaxf(d1, 0.0f));
            const unsigned A1 = pack_h2(fmaxf(d2, 0.0f), fmaxf(d3, 0.0f));
            const unsigned A2 = pack_h2(fmaxf(e0, 0.0f), fmaxf(e1, 0.0f));
            const unsigned A3 = pack_h2(fmaxf(e2, 0.0f), fmaxf(e3, 0.0f));

            mma16816(d0, d1, d2, d3, A0, A1, A2, A3, b2a0, b2a1, bb20, bb21, bb20, bb21);
            mma16816(e0, e1, e2, e3, A0, A1, A2, A3, b2b0, b2b1, bb22, bb23, bb22, bb23);
            d0 = fmaxf(d0, 0.0f); d1 = fmaxf(d1, 0.0f);
            d2 = fmaxf(d2, 0.0f); d3 = fmaxf(d3, 0.0f);
            e0 = fmaxf(e0, 0.0f); e1 = fmaxf(e1, 0.0f);
            e2 = fmaxf(e2, 0.0f); e3 = fmaxf(e3, 0.0f);

            float z0 = d0 * w30; z0 = fmaf(d1, w31, z0);
            z0 = fmaf(e0, w32, z0); z0 = fmaf(e1, w33, z0);   // px = tile*16 + g
            float z1 = d2 * w30; z1 = fmaf(d3, w31, z1);
            z1 = fmaf(e2, w32, z1); z1 = fmaf(e3, w33, z1);   // px = tile*16 + 8 + g

            zr0[t] = z0;
            zr1[t] = z1;
        }

        // quad reductions (independent chains overlap)
        #pragma unroll
        for (int t = 0; t < 2; ++t) {
            zr0[t] += __shfl_xor_sync(0xFFFFFFFFu, zr0[t], 1);
            zr0[t] += __shfl_xor_sync(0xFFFFFFFFu, zr0[t], 2);
            zr1[t] += __shfl_xor_sync(0xFFFFFFFFu, zr1[t], 1);
            zr1[t] += __shfl_xor_sync(0xFFFFFFFFu, zr1[t], 2);
        }

        // distribute: lane L takes pixel tile0*16 + L (L<16 -> tile0, else tile1)
        const int Lm  = lane & 15;
        const int src = (Lm * 4) & 31;
        const float z0lo = __shfl_sync(0xFFFFFFFFu, zr0[0], src);
        const float z0hi = __shfl_sync(0xFFFFFFFFu, zr1[0], src);
        const float z1lo = __shfl_sync(0xFFFFFFFFu, zr0[1], src);
        const float z1hi = __shfl_sync(0xFFFFFFFFu, zr1[1], src);

        const float zlo = (lane < 16) ? z0lo : z1lo;
        const float zhi = (lane < 16) ? z0hi : z1hi;
        const float zv  = ((Lm < 8) ? zlo : zhi) + b3v;

        // full-warp epilogue over 32 contiguous pixels
        const int px = tile0 * 16 + lane;
        float hm = 1.0f / (1.0f + __expf(-zv));
        hm = fminf(fmaxf(hm, EPS_), 1.0f - EPS_);
        float q = 1.0f - tgv;
        q = q * q; q = q * q;
        negAcc += __logf(1.0f - hm) * hm * hm * q;
        if (px == posind) {
            const float om = 1.0f - hm;
            atomicAdd(&g_pos_acc, (double)(__logf(hm) * om * om * mval));
        }
    }

    // ---- block reduction, one double atomic per block ----
    #pragma unroll
    for (int off = 16; off > 0; off >>= 1)
        negAcc += __shfl_down_sync(0xFFFFFFFFu, negAcc, off);
    if (lane == 0) sred[wid] = negAcc;
    __syncthreads();
    if (tid < 32) {
        float v = (tid < 4) ? sred[tid] : 0.0f;
        #pragma unroll
        for (int off = 2; off > 0; off >>= 1)
            v += __shfl_down_sync(0xFFFFFFFFu, v, off);
        if (tid == 0) atomicAdd(&g_neg_acc, (double)v);
    }

    // ---- last-block finalize (threadfence-reduction pattern) ----
    if (tid == 0) {
        __threadfence();
        const unsigned c = atomicAdd(&g_done, 1u);
        s_last = (c == TOTALBLK - 1u) ? 1 : 0;
    }
    __syncthreads();
    if (s_last && tid < 32) {
        float np = 0.0f;
        for (int i = tid; i < BM_; i += 32) np += mask[i];
        #pragma unroll
        for (int off = 16; off > 0; off >>= 1)
            np += __shfl_down_sync(0xFFFFFFFFu, np, off);
        if (tid == 0) {
            const double neg = *(volatile double*)&g_neg_acc;
            const double pos = *(volatile double*)&g_pos_acc;
            double loss;
            if (np == 0.0f) loss = -neg;
            else            loss = -(pos + neg) / (double)fmaxf(np, 1.0f);
            out[0] = (float)loss;
        }
    }
}

extern "C" void kernel_launch(void* const* d_in, const int* in_sizes, int n_in,
                              void* d_out, int out_size)
{
    const float* sch_feat    = (const float*)d_in[0];
    const float* conv_weight = (const float*)d_in[1];
    const float* mask        = (const float*)d_in[2];
    const int*   pre_ind     = (const int*)  d_in[3];
    const float* target      = (const float*)d_in[4];
    const int*   ind         = (const int*)  d_in[5];
    float* out = (float*)d_out;

    feat_frag_kernel<<<dim3(NT16 / 4, B_), 128>>>(sch_feat);

    dim3 grid(GRIDX, BM_);
    sch_loss_main<<<grid, 128>>>(conv_weight, mask, pre_ind, target, ind, out);
}

// round 10
// speedup vs baseline: 1.8992x; 1.0751x over previous
#include <cuda_runtime.h>
#include <cuda_fp16.h>
#include <math.h>

// Fixed problem shapes
#define FCN   16
#define WT    593
#define H_    152
#define W_    272
#define HW_   41344
#define B_    4
#define M_    32
#define BM_   128
#define EPS_  1.0e-4f
#define NT16  2584            // HW_/16 pixel tiles
#define NQUAD 646             // groups of 4 tiles (64 px)
#define GRIDX 20
#define TOTALBLK (GRIDX * BM_)

// Scratch (allocations forbidden)
__device__ double   g_neg_acc;
__device__ double   g_pos_acc;
__device__ unsigned g_done;
__device__ uint4    g_featX[(long long)B_ * NT16 * 32];   // fragment-ordered features

__device__ __forceinline__ unsigned pack_h2(float lo, float hi) {
    unsigned d;
    asm("cvt.rn.f16x2.f32 %0, %1, %2;" : "=r"(d) : "f"(hi), "f"(lo));
    return d;
}
// pack two fp32 to f16x2 then relu in fp16 (identical numerics: rn monotone, 0 exact)
__device__ __forceinline__ unsigned packrelu(float lo, float hi) {
    unsigned u = pack_h2(lo, hi);
    __half2 h = *reinterpret_cast<__half2*>(&u);
    h = __hmax2(h, __half2(__float2half_rn(0.f), __float2half_rn(0.f)));
    return *reinterpret_cast<unsigned*>(&h);
}

// ---- pre-pass: build m16k16 A fragments; also resets accumulators ----
__global__ __launch_bounds__(128)
void feat_frag_kernel(const float* __restrict__ sf) {
    if (blockIdx.x == 0 && blockIdx.y == 0 && threadIdx.x == 0) {
        g_neg_acc = 0.0;
        g_pos_acc = 0.0;
        g_done    = 0u;
    }
    __shared__ float sm[4][16][16];   // [w][c][px]
    const int w    = threadIdx.x >> 5;
    const int t    = threadIdx.x & 31;
    const int tile = blockIdx.x * 4 + w;
    const int b    = blockIdx.y;
    const int base = tile * 16;

    const int c  = t >> 1;
    const int h8 = (t & 1) * 8;
    const float* src = sf + ((long long)b * FCN + c) * HW_ + base + h8;
    const float4 v0 = *(const float4*)src;
    const float4 v1 = *(const float4*)(src + 4);
    sm[w][c][h8 + 0] = v0.x; sm[w][c][h8 + 1] = v0.y;
    sm[w][c][h8 + 2] = v0.z; sm[w][c][h8 + 3] = v0.w;
    sm[w][c][h8 + 4] = v1.x; sm[w][c][h8 + 5] = v1.y;
    sm[w][c][h8 + 6] = v1.z; sm[w][c][h8 + 7] = v1.w;
    __syncwarp();

    const int g  = t >> 2;
    const int tq = t & 3;
    const int k0 = 2 * tq, k1 = k0 + 1, k2 = k0 + 8, k3 = k2 + 1;

    __half2 a0 = __floats2half2_rn(sm[w][k0][g],     sm[w][k1][g]);
    __half2 a1 = __floats2half2_rn(sm[w][k0][g + 8], sm[w][k1][g + 8]);
    __half2 a2 = __floats2half2_rn(sm[w][k2][g],     sm[w][k3][g]);
    __half2 a3 = __floats2half2_rn(sm[w][k2][g + 8], sm[w][k3][g + 8]);

    uint4 o;
    o.x = *(unsigned*)&a0; o.y = *(unsigned*)&a1;
    o.z = *(unsigned*)&a2; o.w = *(unsigned*)&a3;
    g_featX[((long long)b * NT16 + tile) * 32 + t] = o;
}

__device__ __forceinline__ void mma16816(
    float& d0, float& d1, float& d2, float& d3,
    unsigned a0, unsigned a1, unsigned a2, unsigned a3,
    unsigned b0, unsigned b1,
    float c0, float c1, float c2, float c3)
{
    asm("mma.sync.aligned.m16n8k16.row.col.f32.f16.f16.f32 "
        "{%0,%1,%2,%3}, {%4,%5,%6,%7}, {%8,%9}, {%10,%11,%12,%13};"
        : "=f"(d0), "=f"(d1), "=f"(d2), "=f"(d3)
        : "r"(a0), "r"(a1), "r"(a2), "r"(a3), "r"(b0), "r"(b1),
          "f"(c0), "f"(c1), "f"(c2), "f"(c3));
}

__global__ __launch_bounds__(128, 4)
void sch_loss_main(const float* __restrict__ conv_weight,
                   const float* __restrict__ mask,
                   const int*   __restrict__ pre_ind,
                   const float* __restrict__ target,
                   const int*   __restrict__ ind,
                   float* __restrict__ out)
{
    __shared__ __align__(4) __half w1h[256];   // [o*16 + c], c<16
    __shared__ __align__(4) __half w2h[256];   // [o*16 + c]
    __shared__ float b1f[16], b2f[16], w3f[16], wxf[16], wyf[16];
    __shared__ float b3s;
    __shared__ float sred[4];
    __shared__ int   s_last;

    const int bm   = blockIdx.y;
    const int b    = bm >> 5;
    const int tid  = threadIdx.x;
    const int wid  = tid >> 5;
    const int lane = tid & 31;
    const int pi   = pre_ind[bm];

    // ---- prologue: gather + route 593 weights ----
    for (int idx = tid; idx < WT; idx += 128) {
        const float v = conv_weight[((long long)b * WT + idx) * HW_ + pi];
        if (idx < 288) {
            const int o = idx / 18, c = idx % 18;
            if      (c < 16)  w1h[o * 16 + c] = __float2half_rn(v);
            else if (c == 16) wxf[o] = v;
            else              wyf[o] = v;
        } else if (idx < 304) b1f[idx - 288] = v;
        else if (idx < 560)   w2h[idx - 304] = __float2half_rn(v);
        else if (idx < 576)   b2f[idx - 560] = v;
        else if (idx < 592)   w3f[idx - 576] = v;
        else                  b3s = v;
    }
    __syncthreads();

    const int g  = lane >> 2;
    const int tq = lane & 3;
    const int k0 = 2 * tq, k2 = k0 + 8;
    const int k1 = k0 + 1, k3 = k2 + 1;

    // B frags (col-major k16n8), fixed for the block
    const unsigned b1a0 = *(const unsigned*)&w1h[g * 16 + k0];
    const unsigned b1a1 = *(const unsigned*)&w1h[g * 16 + k2];
    const unsigned b1b0 = *(const unsigned*)&w1h[(g + 8) * 16 + k0];
    const unsigned b1b1 = *(const unsigned*)&w1h[(g + 8) * 16 + k2];
    const unsigned b2a0 = *(const unsigned*)&w2h[g * 16 + k0];
    const unsigned b2a1 = *(const unsigned*)&w2h[g * 16 + k2];
    const unsigned b2b0 = *(const unsigned*)&w2h[(g + 8) * 16 + k0];
    const unsigned b2b1 = *(const unsigned*)&w2h[(g + 8) * 16 + k2];
    // layer3 B: w3 broadcast into ALL 8 columns -> every thread same frag
    const unsigned b30 = pack_h2(w3f[k0], w3f[k1]);
    const unsigned b31 = pack_h2(w3f[k2], w3f[k3]);

    const float bb10 = b1f[k0], bb11 = b1f[k1], bb12 = b1f[k2], bb13 = b1f[k3];
    const float bb20 = b2f[k0], bb21 = b2f[k1], bb22 = b2f[k2], bb23 = b2f[k3];
    const float wx0 = wxf[k0], wx1 = wxf[k1], wx2 = wxf[k2], wx3 = wxf[k3];
    const float wy0 = wyf[k0], wy1 = wyf[k1], wy2 = wyf[k2], wy3 = wyf[k3];
    const float b3v = b3s;

    const float* __restrict__ tg = target + (long long)bm * HW_;
    const uint4* __restrict__ fx = g_featX + (long long)b * NT16 * 32;
    const int   posind = ind[bm];
    const float mval   = mask[bm];

    const float x0 = (float)(pi % W_);
    const float y0 = (float)pi / (float)W_;     // float division, matching reference
    const float inv128 = 1.0f / 128.0f;

    float negAcc = 0.0f;

    for (int q = blockIdx.x * 4 + wid; q < NQUAD; q += GRIDX * 4) {
        const int tile0 = q * 4;
        const int base  = tile0 * 16;

        // batched independent loads (MLP = 6)
        const uint4 af0 = fx[(long long)(tile0 + 0) * 32 + lane];
        const uint4 af1 = fx[(long long)(tile0 + 1) * 32 + lane];
        const uint4 af2 = fx[(long long)(tile0 + 2) * 32 + lane];
        const uint4 af3 = fx[(long long)(tile0 + 3) * 32 + lane];
        // this thread's epilogue pixels: tile tq, rows g and g+8
        const int  pxlo = base + tq * 16 + g;
        const float tlo = tg[pxlo];
        const float thi = tg[pxlo + 8];

        float zlo = 0.0f, zhi = 0.0f;

        #pragma unroll
        for (int t = 0; t < 4; ++t) {
            const int  tile = tile0 + t;
            const uint4 af  = (t == 0) ? af0 : (t == 1) ? af1 : (t == 2) ? af2 : af3;

            const float xrl = ((float)((tile % 17) * 16 + g) - x0) * inv128;
            const float xrh = xrl + 8.0f * inv128;
            const float yrv = ((float)(tile / 17) - y0) * inv128;

            const float cy0 = fmaf(yrv, wy0, bb10);
            const float cy1 = fmaf(yrv, wy1, bb11);
            const float cy2 = fmaf(yrv, wy2, bb12);
            const float cy3 = fmaf(yrv, wy3, bb13);

            float d0, d1, d2, d3, e0, e1, e2, e3;
            // layer 1
            mma16816(d0, d1, d2, d3, af.x, af.y, af.z, af.w, b1a0, b1a1, cy0, cy1, cy0, cy1);
            mma16816(e0, e1, e2, e3, af.x, af.y, af.z, af.w, b1b0, b1b1, cy2, cy3, cy2, cy3);
            d0 = fmaf(xrl, wx0, d0); d1 = fmaf(xrl, wx1, d1);
            d2 = fmaf(xrh, wx0, d2); d3 = fmaf(xrh, wx1, d3);
            e0 = fmaf(xrl, wx2, e0); e1 = fmaf(xrl, wx3, e1);
            e2 = fmaf(xrh, wx2, e2); e3 = fmaf(xrh, wx3, e3);

            const unsigned A0 = packrelu(d0, d1);
            const unsigned A1 = packrelu(d2, d3);
            const unsigned A2 = packrelu(e0, e1);
            const unsigned A3 = packrelu(e2, e3);

            // layer 2
            mma16816(d0, d1, d2, d3, A0, A1, A2, A3, b2a0, b2a1, bb20, bb21, bb20, bb21);
            mma16816(e0, e1, e2, e3, A0, A1, A2, A3, b2b0, b2b1, bb22, bb23, bb22, bb23);

            const unsigned C0 = packrelu(d0, d1);
            const unsigned C1 = packrelu(d2, d3);
            const unsigned C2 = packrelu(e0, e1);
            const unsigned C3 = packrelu(e2, e3);

            // layer 3: w3 in every column -> z in every D register; keep if t == tq
            float z0, z1, z2, z3;
            mma16816(z0, z1, z2, z3, C0, C1, C2, C3, b30, b31, 0.f, 0.f, 0.f, 0.f);
            if (t == tq) { zlo = z0; zhi = z2; }
        }

        // ---- epilogue: 2 pixels per thread, no shuffles ----
        {
            const float zv = zlo + b3v;
            float hm = 1.0f / (1.0f + __expf(-zv));
            hm = fminf(fmaxf(hm, EPS_), 1.0f - EPS_);
            float qv = 1.0f - tlo;
            qv = qv * qv; qv = qv * qv;
            negAcc += __logf(1.0f - hm) * hm * hm * qv;
            if (pxlo == posind) {
                const float om = 1.0f - hm;
                atomicAdd(&g_pos_acc, (double)(__logf(hm) * om * om * mval));
            }
        }
        {
            const float zv = zhi + b3v;
            float hm = 1.0f / (1.0f + __expf(-zv));
            hm = fminf(fmaxf(hm, EPS_), 1.0f - EPS_);
            float qv = 1.0f - thi;
            qv = qv * qv; qv = qv * qv;
            negAcc += __logf(1.0f - hm) * hm * hm * qv;
            if (pxlo + 8 == posind) {
                const float om = 1.0f - hm;
                atomicAdd(&g_pos_acc, (double)(__logf(hm) * om * om * mval));
            }
        }
    }

    // ---- block reduction, one double atomic per block ----
    #pragma unroll
    for (int off = 16; off > 0; off >>= 1)
        negAcc += __shfl_down_sync(0xFFFFFFFFu, negAcc, off);
    if (lane == 0) sred[wid] = negAcc;
    __syncthreads();
    if (tid < 32) {
        float v = (tid < 4) ? sred[tid] : 0.0f;
        #pragma unroll
        for (int off = 2; off > 0; off >>= 1)
            v += __shfl_down_sync(0xFFFFFFFFu, v, off);
        if (tid == 0) atomicAdd(&g_neg_acc, (double)v);
    }

    // ---- last-block finalize ----
    if (tid == 0) {
        __threadfence();
        const unsigned c = atomicAdd(&g_done, 1u);
        s_last = (c == TOTALBLK - 1u) ? 1 : 0;
    }
    __syncthreads();
    if (s_last && tid < 32) {
        float np = 0.0f;
        for (int i = tid; i < BM_; i += 32) np += mask[i];
        #pragma unroll
        for (int off = 16; off > 0; off >>= 1)
            np += __shfl_down_sync(0xFFFFFFFFu, np, off);
        if (tid == 0) {
            const double neg = *(volatile double*)&g_neg_acc;
            const double pos = *(volatile double*)&g_pos_acc;
            double loss;
            if (np == 0.0f) loss = -neg;
            else            loss = -(pos + neg) / (double)fmaxf(np, 1.0f);
            out[0] = (float)loss;
        }
    }
}

extern "C" void kernel_launch(void* const* d_in, const int* in_sizes, int n_in,
                              void* d_out, int out_size)
{
    const float* sch_feat    = (const float*)d_in[0];
    const float* conv_weight = (const float*)d_in[1];
    const float* mask        = (const float*)d_in[2];
    const int*   pre_ind     = (const int*)  d_in[3];
    const float* target      = (const float*)d_in[4];
    const int*   ind         = (const int*)  d_in[5];
    float* out = (float*)d_out;

    feat_frag_kernel<<<dim3(NT16 / 4, B_), 128>>>(sch_feat);

    dim3 grid(GRIDX, BM_);
    sch_loss_main<<<grid, 128>>>(conv_weight, mask, pre_ind, target, ind, out);
}

// round 11
// speedup vs baseline: 1.9133x; 1.0075x over previous
#include <cuda_runtime.h>
#include <cuda_fp16.h>
#include <math.h>

// Fixed problem shapes
#define FCN   16
#define WT    593
#define H_    152
#define W_    272
#define HW_   41344
#define B_    4
#define M_    32
#define BM_   128
#define EPS_  1.0e-4f
#define NT16  2584            // HW_/16 pixel tiles
#define NQUAD 646             // groups of 4 tiles (64 px)
#define GRIDX 20
#define TOTALBLK (GRIDX * BM_)

// Scratch (allocations forbidden)
__device__ double   g_neg_acc;
__device__ double   g_pos_acc;
__device__ unsigned g_done;
__device__ uint4    g_featX[(long long)B_ * NT16 * 32];   // fragment-ordered features

__device__ __forceinline__ unsigned pack_h2(float lo, float hi) {
    unsigned d;
    asm("cvt.rn.f16x2.f32 %0, %1, %2;" : "=r"(d) : "f"(hi), "f"(lo));
    return d;
}
// pack two fp32 to f16x2 then relu in fp16 (identical numerics: rn monotone, 0 exact)
__device__ __forceinline__ unsigned packrelu(float lo, float hi) {
    unsigned u = pack_h2(lo, hi);
    __half2 h = *reinterpret_cast<__half2*>(&u);
    h = __hmax2(h, __half2(__float2half_rn(0.f), __float2half_rn(0.f)));
    return *reinterpret_cast<unsigned*>(&h);
}

// ---- pre-pass: build m16k16 A fragments; also resets accumulators ----
__global__ __launch_bounds__(128)
void feat_frag_kernel(const float* __restrict__ sf) {
    if (blockIdx.x == 0 && blockIdx.y == 0 && threadIdx.x == 0) {
        g_neg_acc = 0.0;
        g_pos_acc = 0.0;
        g_done    = 0u;
    }
    __shared__ float sm[4][16][16];   // [w][c][px]
    const int w    = threadIdx.x >> 5;
    const int t    = threadIdx.x & 31;
    const int tile = blockIdx.x * 4 + w;
    const int b    = blockIdx.y;
    const int base = tile * 16;

    const int c  = t >> 1;
    const int h8 = (t & 1) * 8;
    const float* src = sf + ((long long)b * FCN + c) * HW_ + base + h8;
    const float4 v0 = *(const float4*)src;
    const float4 v1 = *(const float4*)(src + 4);
    sm[w][c][h8 + 0] = v0.x; sm[w][c][h8 + 1] = v0.y;
    sm[w][c][h8 + 2] = v0.z; sm[w][c][h8 + 3] = v0.w;
    sm[w][c][h8 + 4] = v1.x; sm[w][c][h8 + 5] = v1.y;
    sm[w][c][h8 + 6] = v1.z; sm[w][c][h8 + 7] = v1.w;
    __syncwarp();

    const int g  = t >> 2;
    const int tq = t & 3;
    const int k0 = 2 * tq, k1 = k0 + 1, k2 = k0 + 8, k3 = k2 + 1;

    __half2 a0 = __floats2half2_rn(sm[w][k0][g],     sm[w][k1][g]);
    __half2 a1 = __floats2half2_rn(sm[w][k0][g + 8], sm[w][k1][g + 8]);
    __half2 a2 = __floats2half2_rn(sm[w][k2][g],     sm[w][k3][g]);
    __half2 a3 = __floats2half2_rn(sm[w][k2][g + 8], sm[w][k3][g + 8]);

    uint4 o;
    o.x = *(unsigned*)&a0; o.y = *(unsigned*)&a1;
    o.z = *(unsigned*)&a2; o.w = *(unsigned*)&a3;
    g_featX[((long long)b * NT16 + tile) * 32 + t] = o;
}

__device__ __forceinline__ void mma16816(
    float& d0, float& d1, float& d2, float& d3,
    unsigned a0, unsigned a1, unsigned a2, unsigned a3,
    unsigned b0, unsigned b1,
    float c0, float c1, float c2, float c3)
{
    asm("mma.sync.aligned.m16n8k16.row.col.f32.f16.f16.f32 "
        "{%0,%1,%2,%3}, {%4,%5,%6,%7}, {%8,%9}, {%10,%11,%12,%13};"
        : "=f"(d0), "=f"(d1), "=f"(d2), "=f"(d3)
        : "r"(a0), "r"(a1), "r"(a2), "r"(a3), "r"(b0), "r"(b1),
          "f"(c0), "f"(c1), "f"(c2), "f"(c3));
}

__global__ __launch_bounds__(128, 4)
void sch_loss_main(const float* __restrict__ conv_weight,
                   const float* __restrict__ mask,
                   const int*   __restrict__ pre_ind,
                   const float* __restrict__ target,
                   const int*   __restrict__ ind,
                   float* __restrict__ out)
{
    __shared__ __align__(4) __half w1h[256];   // [o*16 + c], c<16
    __shared__ __align__(4) __half w2h[256];   // [o*16 + c]
    __shared__ float b1f[16], b2f[16], w3f[16], wxf[16], wyf[16];
    __shared__ float b3s;
    __shared__ float sred[4];
    __shared__ int   s_last;

    const int bm   = blockIdx.y;
    const int b    = bm >> 5;
    const int tid  = threadIdx.x;
    const int wid  = tid >> 5;
    const int lane = tid & 31;
    const int pi   = pre_ind[bm];

    // ---- prologue: gather + route 593 weights ----
    for (int idx = tid; idx < WT; idx += 128) {
        const float v = conv_weight[((long long)b * WT + idx) * HW_ + pi];
        if (idx < 288) {
            const int o = idx / 18, c = idx % 18;
            if      (c < 16)  w1h[o * 16 + c] = __float2half_rn(v);
            else if (c == 16) wxf[o] = v;
            else              wyf[o] = v;
        } else if (idx < 304) b1f[idx - 288] = v;
        else if (idx < 560)   w2h[idx - 304] = __float2half_rn(v);
        else if (idx < 576)   b2f[idx - 560] = v;
        else if (idx < 592)   w3f[idx - 576] = v;
        else                  b3s = v;
    }
    __syncthreads();

    const int g  = lane >> 2;
    const int tq = lane & 3;
    const int k0 = 2 * tq, k2 = k0 + 8;
    const int k1 = k0 + 1, k3 = k2 + 1;

    // B frags (col-major k16n8), fixed for the block
    const unsigned b1a0 = *(const unsigned*)&w1h[g * 16 + k0];
    const unsigned b1a1 = *(const unsigned*)&w1h[g * 16 + k2];
    const unsigned b1b0 = *(const unsigned*)&w1h[(g + 8) * 16 + k0];
    const unsigned b1b1 = *(const unsigned*)&w1h[(g + 8) * 16 + k2];
    const unsigned b2a0 = *(const unsigned*)&w2h[g * 16 + k0];
    const unsigned b2a1 = *(const unsigned*)&w2h[g * 16 + k2];
    const unsigned b2b0 = *(const unsigned*)&w2h[(g + 8) * 16 + k0];
    const unsigned b2b1 = *(const unsigned*)&w2h[(g + 8) * 16 + k2];
    // layer3 B: w3 broadcast into ALL 8 columns -> every thread same frag
    const unsigned b30 = pack_h2(w3f[k0], w3f[k1]);
    const unsigned b31 = pack_h2(w3f[k2], w3f[k3]);

    const float bb10 = b1f[k0], bb11 = b1f[k1], bb12 = b1f[k2], bb13 = b1f[k3];
    const float bb20 = b2f[k0], bb21 = b2f[k1], bb22 = b2f[k2], bb23 = b2f[k3];
    const float wx0 = wxf[k0], wx1 = wxf[k1], wx2 = wxf[k2], wx3 = wxf[k3];
    const float wy0 = wyf[k0], wy1 = wyf[k1], wy2 = wyf[k2], wy3 = wyf[k3];
    const float b3v = b3s;

    const float* __restrict__ tg = target + (long long)bm * HW_;
    const uint4* __restrict__ fx = g_featX + (long long)b * NT16 * 32;
    const int   posind = ind[bm];
    const float mval   = mask[bm];

    const float x0 = (float)(pi % W_);
    const float y0 = (float)pi / (float)W_;     // float division, matching reference
    const float inv128 = 1.0f / 128.0f;

    float negAcc = 0.0f;

    for (int q = blockIdx.x * 4 + wid; q < NQUAD; q += GRIDX * 4) {
        const int tile0 = q * 4;
        const int base  = tile0 * 16;

        // ---- stage 0: batched independent loads (MLP = 6) ----
        uint4 af[4];
        af[0] = fx[(long long)(tile0 + 0) * 32 + lane];
        af[1] = fx[(long long)(tile0 + 1) * 32 + lane];
        af[2] = fx[(long long)(tile0 + 2) * 32 + lane];
        af[3] = fx[(long long)(tile0 + 3) * 32 + lane];
        const int  pxlo = base + tq * 16 + g;
        const float tlo = tg[pxlo];
        const float thi = tg[pxlo + 8];

        float d[4][4], e[4][4];

        // ---- stage 1: ALL layer-1 mmas back-to-back (8 independent) ----
        #pragma unroll
        for (int t = 0; t < 4; ++t) {
            const int  tile = tile0 + t;
            const float yrv = ((float)(tile / 17) - y0) * inv128;
            const float cy0 = fmaf(yrv, wy0, bb10);
            const float cy1 = fmaf(yrv, wy1, bb11);
            const float cy2 = fmaf(yrv, wy2, bb12);
            const float cy3 = fmaf(yrv, wy3, bb13);
            mma16816(d[t][0], d[t][1], d[t][2], d[t][3],
                     af[t].x, af[t].y, af[t].z, af[t].w, b1a0, b1a1, cy0, cy1, cy0, cy1);
            mma16816(e[t][0], e[t][1], e[t][2], e[t][3],
                     af[t].x, af[t].y, af[t].z, af[t].w, b1b0, b1b1, cy2, cy3, cy2, cy3);
        }

        // ---- stage 1b: coord x correction + pack+relu (independent per tile) ----
        unsigned A[4][4];
        #pragma unroll
        for (int t = 0; t < 4; ++t) {
            const int  tile = tile0 + t;
            const float xrl = ((float)((tile % 17) * 16 + g) - x0) * inv128;
            const float xrh = xrl + 8.0f * inv128;
            A[t][0] = packrelu(fmaf(xrl, wx0, d[t][0]), fmaf(xrl, wx1, d[t][1]));
            A[t][1] = packrelu(fmaf(xrh, wx0, d[t][2]), fmaf(xrh, wx1, d[t][3]));
            A[t][2] = packrelu(fmaf(xrl, wx2, e[t][0]), fmaf(xrl, wx3, e[t][1]));
            A[t][3] = packrelu(fmaf(xrh, wx2, e[t][2]), fmaf(xrh, wx3, e[t][3]));
        }

        // ---- stage 2: ALL layer-2 mmas back-to-back (8 independent) ----
        #pragma unroll
        for (int t = 0; t < 4; ++t) {
            mma16816(d[t][0], d[t][1], d[t][2], d[t][3],
                     A[t][0], A[t][1], A[t][2], A[t][3], b2a0, b2a1, bb20, bb21, bb20, bb21);
            mma16816(e[t][0], e[t][1], e[t][2], e[t][3],
                     A[t][0], A[t][1], A[t][2], A[t][3], b2b0, b2b1, bb22, bb23, bb22, bb23);
        }

        // ---- stage 2b: pack+relu ----
        #pragma unroll
        for (int t = 0; t < 4; ++t) {
            A[t][0] = packrelu(d[t][0], d[t][1]);
            A[t][1] = packrelu(d[t][2], d[t][3]);
            A[t][2] = packrelu(e[t][0], e[t][1]);
            A[t][3] = packrelu(e[t][2], e[t][3]);
        }

        // ---- stage 3: ALL layer-3 mmas back-to-back (4 independent) ----
        float zlo = 0.0f, zhi = 0.0f;
        #pragma unroll
        for (int t = 0; t < 4; ++t) {
            float z0, z1, z2, z3;
            mma16816(z0, z1, z2, z3,
                     A[t][0], A[t][1], A[t][2], A[t][3], b30, b31, 0.f, 0.f, 0.f, 0.f);
            if (t == tq) { zlo = z0; zhi = z2; }
        }

        // ---- epilogue: 2 pixels per thread, no shuffles ----
        {
            const float zv = zlo + b3v;
            float hm = 1.0f / (1.0f + __expf(-zv));
            hm = fminf(fmaxf(hm, EPS_), 1.0f - EPS_);
            float qv = 1.0f - tlo;
            qv = qv * qv; qv = qv * qv;
            negAcc += __logf(1.0f - hm) * hm * hm * qv;
            if (pxlo == posind) {
                const float om = 1.0f - hm;
                atomicAdd(&g_pos_acc, (double)(__logf(hm) * om * om * mval));
            }
        }
        {
            const float zv = zhi + b3v;
            float hm = 1.0f / (1.0f + __expf(-zv));
            hm = fminf(fmaxf(hm, EPS_), 1.0f - EPS_);
            float qv = 1.0f - thi;
            qv = qv * qv; qv = qv * qv;
            negAcc += __logf(1.0f - hm) * hm * hm * qv;
            if (pxlo + 8 == posind) {
                const float om = 1.0f - hm;
                atomicAdd(&g_pos_acc, (double)(__logf(hm) * om * om * mval));
            }
        }
    }

    // ---- block reduction, one double atomic per block ----
    #pragma unroll
    for (int off = 16; off > 0; off >>= 1)
        negAcc += __shfl_down_sync(0xFFFFFFFFu, negAcc, off);
    if (lane == 0) sred[wid] = negAcc;
    __syncthreads();
    if (tid < 32) {
        float v = (tid < 4) ? sred[tid] : 0.0f;
        #pragma unroll
        for (int off = 2; off > 0; off >>= 1)
            v += __shfl_down_sync(0xFFFFFFFFu, v, off);
        if (tid == 0) atomicAdd(&g_neg_acc, (double)v);
    }

    // ---- last-block finalize ----
    if (tid == 0) {
        __threadfence();
        const unsigned c = atomicAdd(&g_done, 1u);
        s_last = (c == TOTALBLK - 1u) ? 1 : 0;
    }
    __syncthreads();
    if (s_last && tid < 32) {
        float np = 0.0f;
        for (int i = tid; i < BM_; i += 32) np += mask[i];
        #pragma unroll
        for (int off = 16; off > 0; off >>= 1)
            np += __shfl_down_sync(0xFFFFFFFFu, np, off);
        if (tid == 0) {
            const double neg = *(volatile double*)&g_neg_acc;
            const double pos = *(volatile double*)&g_pos_acc;
            double loss;
            if (np == 0.0f) loss = -neg;
            else            loss = -(pos + neg) / (double)fmaxf(np, 1.0f);
            out[0] = (float)loss;
        }
    }
}

extern "C" void kernel_launch(void* const* d_in, const int* in_sizes, int n_in,
                              void* d_out, int out_size)
{
    const float* sch_feat    = (const float*)d_in[0];
    const float* conv_weight = (const float*)d_in[1];
    const float* mask        = (const float*)d_in[2];
    const int*   pre_ind     = (const int*)  d_in[3];
    const float* target      = (const float*)d_in[4];
    const int*   ind         = (const int*)  d_in[5];
    float* out = (float*)d_out;

    feat_frag_kernel<<<dim3(NT16 / 4, B_), 128>>>(sch_feat);

    dim3 grid(GRIDX, BM_);
    sch_loss_main<<<grid, 128>>>(conv_weight, mask, pre_ind, target, ind, out);
}

// round 12
// speedup vs baseline: 2.0000x; 1.0453x over previous
#include <cuda_runtime.h>
#include <cuda_fp16.h>
#include <math.h>

// Fixed problem shapes
#define FCN   16
#define WT    593
#define H_    152
#define W_    272
#define HW_   41344
#define B_    4
#define M_    32
#define BM_   128
#define EPS_  1.0e-4f
#define NT16  2584            // HW_/16 pixel tiles
#define NQUAD 646             // groups of 4 tiles (64 px)
#define GRIDX 20
#define TOTALBLK (GRIDX * BM_)

// Scratch (allocations forbidden)
__device__ double   g_neg_acc;
__device__ double   g_pos_acc;
__device__ unsigned g_done;
__device__ uint4    g_featX[(long long)B_ * NT16 * 32];   // fragment-ordered features

__device__ __forceinline__ unsigned pack_h2(float lo, float hi) {
    unsigned d;
    asm("cvt.rn.f16x2.f32 %0, %1, %2;" : "=r"(d) : "f"(hi), "f"(lo));
    return d;
}
// pack two fp32 to f16x2 then relu in fp16 (identical numerics: rn monotone, 0 exact)
__device__ __forceinline__ unsigned packrelu(float lo, float hi) {
    unsigned u = pack_h2(lo, hi);
    __half2 h = *reinterpret_cast<__half2*>(&u);
    h = __hmax2(h, __half2(__float2half_rn(0.f), __float2half_rn(0.f)));
    return *reinterpret_cast<unsigned*>(&h);
}

// ---- pre-pass: build m16k16 A fragments; also resets accumulators ----
__global__ __launch_bounds__(128)
void feat_frag_kernel(const float* __restrict__ sf) {
    if (blockIdx.x == 0 && blockIdx.y == 0 && threadIdx.x == 0) {
        g_neg_acc = 0.0;
        g_pos_acc = 0.0;
        g_done    = 0u;
    }
    __shared__ float sm[4][16][16];   // [w][c][px]
    const int w    = threadIdx.x >> 5;
    const int t    = threadIdx.x & 31;
    const int tile = blockIdx.x * 4 + w;
    const int b    = blockIdx.y;
    const int base = tile * 16;

    const int c  = t >> 1;
    const int h8 = (t & 1) * 8;
    const float* src = sf + ((long long)b * FCN + c) * HW_ + base + h8;
    const float4 v0 = *(const float4*)src;
    const float4 v1 = *(const float4*)(src + 4);
    sm[w][c][h8 + 0] = v0.x; sm[w][c][h8 + 1] = v0.y;
    sm[w][c][h8 + 2] = v0.z; sm[w][c][h8 + 3] = v0.w;
    sm[w][c][h8 + 4] = v1.x; sm[w][c][h8 + 5] = v1.y;
    sm[w][c][h8 + 6] = v1.z; sm[w][c][h8 + 7] = v1.w;
    __syncwarp();

    const int g  = t >> 2;
    const int tq = t & 3;
    const int k0 = 2 * tq, k1 = k0 + 1, k2 = k0 + 8, k3 = k2 + 1;

    __half2 a0 = __floats2half2_rn(sm[w][k0][g],     sm[w][k1][g]);
    __half2 a1 = __floats2half2_rn(sm[w][k0][g + 8], sm[w][k1][g + 8]);
    __half2 a2 = __floats2half2_rn(sm[w][k2][g],     sm[w][k3][g]);
    __half2 a3 = __floats2half2_rn(sm[w][k2][g + 8], sm[w][k3][g + 8]);

    uint4 o;
    o.x = *(unsigned*)&a0; o.y = *(unsigned*)&a1;
    o.z = *(unsigned*)&a2; o.w = *(unsigned*)&a3;
    g_featX[((long long)b * NT16 + tile) * 32 + t] = o;
}

__device__ __forceinline__ void mma16816(
    float& d0, float& d1, float& d2, float& d3,
    unsigned a0, unsigned a1, unsigned a2, unsigned a3,
    unsigned b0, unsigned b1,
    float c0, float c1, float c2, float c3)
{
    asm("mma.sync.aligned.m16n8k16.row.col.f32.f16.f16.f32 "
        "{%0,%1,%2,%3}, {%4,%5,%6,%7}, {%8,%9}, {%10,%11,%12,%13};"
        : "=f"(d0), "=f"(d1), "=f"(d2), "=f"(d3)
        : "r"(a0), "r"(a1), "r"(a2), "r"(a3), "r"(b0), "r"(b1),
          "f"(c0), "f"(c1), "f"(c2), "f"(c3));
}

__global__ __launch_bounds__(128, 6)
void sch_loss_main(const float* __restrict__ conv_weight,
                   const float* __restrict__ mask,
                   const int*   __restrict__ pre_ind,
                   const float* __restrict__ target,
                   const int*   __restrict__ ind,
                   float* __restrict__ out)
{
    __shared__ __align__(4) __half w1h[256];   // [o*16 + c], c<16
    __shared__ __align__(4) __half w2h[256];   // [o*16 + c]
    __shared__ float b1f[16], b2f[16], w3f[16], wxf[16], wyf[16];
    __shared__ float b1c[16];                  // bias with coord offset folded in
    __shared__ float b3s;
    __shared__ float sred[4];
    __shared__ int   s_last;

    const int bm   = blockIdx.y;
    const int b    = bm >> 5;
    const int tid  = threadIdx.x;
    const int wid  = tid >> 5;
    const int lane = tid & 31;
    const int pi   = pre_ind[bm];

    const float x0 = (float)(pi % W_);
    const float y0 = (float)pi / (float)W_;     // float division, matching reference
    const float inv128 = 1.0f / 128.0f;

    // ---- prologue: gather + route 593 weights ----
    for (int idx = tid; idx < WT; idx += 128) {
        const float v = conv_weight[((long long)b * WT + idx) * HW_ + pi];
        if (idx < 288) {
            const int o = idx / 18, c = idx % 18;
            if      (c < 16)  w1h[o * 16 + c] = __float2half_rn(v);
            else if (c == 16) wxf[o] = v;
            else              wyf[o] = v;
        } else if (idx < 304) b1f[idx - 288] = v;
        else if (idx < 560)   w2h[idx - 304] = __float2half_rn(v);
        else if (idx < 576)   b2f[idx - 560] = v;
        else if (idx < 592)   w3f[idx - 576] = v;
        else                  b3s = v;
    }
    __syncthreads();
    // fold -(wx*x0 + wy*y0)/128 into layer-1 bias, in fp32
    if (tid < 16)
        b1c[tid] = b1f[tid] - (wxf[tid] * x0 + wyf[tid] * y0) * inv128;
    __syncthreads();

    const int g  = lane >> 2;
    const int tq = lane & 3;
    const bool tq0 = (tq == 0);
    const int k0 = 2 * tq, k2 = k0 + 8;
    const int k1 = k0 + 1, k3 = k2 + 1;

    // B frags (col-major k16n8), fixed for the block
    const unsigned b1a0 = *(const unsigned*)&w1h[g * 16 + k0];
    const unsigned b1a1 = *(const unsigned*)&w1h[g * 16 + k2];
    const unsigned b1b0 = *(const unsigned*)&w1h[(g + 8) * 16 + k0];
    const unsigned b1b1 = *(const unsigned*)&w1h[(g + 8) * 16 + k2];
    const unsigned b2a0 = *(const unsigned*)&w2h[g * 16 + k0];
    const unsigned b2a1 = *(const unsigned*)&w2h[g * 16 + k2];
    const unsigned b2b0 = *(const unsigned*)&w2h[(g + 8) * 16 + k0];
    const unsigned b2b1 = *(const unsigned*)&w2h[(g + 8) * 16 + k2];
    // layer3 B: w3 broadcast into ALL 8 columns
    const unsigned b30 = pack_h2(w3f[k0], w3f[k1]);
    const unsigned b31 = pack_h2(w3f[k2], w3f[k3]);
    // coord-mma B frags: rows k=0,1 (wx, wy) live on tq==0 threads; rest zero
    const unsigned cbA = tq0 ? pack_h2(wxf[g],     wyf[g])     : 0u;
    const unsigned cbB = tq0 ? pack_h2(wxf[g + 8], wyf[g + 8]) : 0u;

    const float bcA0 = b1c[k0], bcA1 = b1c[k1], bcB0 = b1c[k2], bcB1 = b1c[k3];
    const float bb20 = b2f[k0], bb21 = b2f[k1], bb22 = b2f[k2], bb23 = b2f[k3];
    const float b3v = b3s;

    const float* __restrict__ tg = target + (long long)bm * HW_;
    const char*  __restrict__ fxb = (const char*)(g_featX + (long long)b * NT16 * 32)
                                    + (unsigned)lane * 16u;
    const int   posind = ind[bm];
    const float mval   = mask[bm];
    const float gx = (float)g * inv128;   // g/128, invariant

    float negAcc = 0.0f;

    for (int q = blockIdx.x * 4 + wid; q < NQUAD; q += GRIDX * 4) {
        const int tile0 = q * 4;

        // ---- batched independent loads (32-bit offsets) ----
        const unsigned off0 = (unsigned)tile0 * 512u;
        const uint4 af0 = *(const uint4*)(fxb + off0);
        const uint4 af1 = *(const uint4*)(fxb + off0 + 512u);
        const uint4 af2 = *(const uint4*)(fxb + off0 + 1024u);
        const uint4 af3 = *(const uint4*)(fxb + off0 + 1536u);
        const int  pxlo = tile0 * 16 + tq * 16 + g;
        const float tlo = tg[pxlo];
        const float thi = tg[pxlo + 8];

        // coords: one div-by-17 per quad, incremental within
        int   col = tile0 % 17;
        float ya  = (float)(tile0 / 17) * inv128;   // exact (int/2^7)
        float xq  = (float)col * 0.125f;

        float zlo = 0.0f, zhi = 0.0f;

        #pragma unroll
        for (int t = 0; t < 4; ++t) {
            const uint4 af = (t == 0) ? af0 : (t == 1) ? af1 : (t == 2) ? af2 : af3;

            // coord A frag: (x/128, y/128) on tq==0 lanes; exact in fp16
            const float xal = xq + gx;
            const unsigned caLo = tq0 ? pack_h2(xal,           ya) : 0u;
            const unsigned caHi = tq0 ? pack_h2(xal + 0.0625f, ya) : 0u;

            float d0, d1, d2, d3, e0, e1, e2, e3;
            // layer 1 (bias folded with coord offset) + coord mma accumulate
            mma16816(d0, d1, d2, d3, af.x, af.y, af.z, af.w, b1a0, b1a1,
                     bcA0, bcA1, bcA0, bcA1);
            mma16816(e0, e1, e2, e3, af.x, af.y, af.z, af.w, b1b0, b1b1,
                     bcB0, bcB1, bcB0, bcB1);
            mma16816(d0, d1, d2, d3, caLo, caHi, 0u, 0u, cbA, 0u, d0, d1, d2, d3);
            mma16816(e0, e1, e2, e3, caLo, caHi, 0u, 0u, cbB, 0u, e0, e1, e2, e3);

            const unsigned A0 = packrelu(d0, d1);
            const unsigned A1 = packrelu(d2, d3);
            const unsigned A2 = packrelu(e0, e1);
            const unsigned A3 = packrelu(e2, e3);

            // layer 2
            mma16816(d0, d1, d2, d3, A0, A1, A2, A3, b2a0, b2a1, bb20, bb21, bb20, bb21);
            mma16816(e0, e1, e2, e3, A0, A1, A2, A3, b2b0, b2b1, bb22, bb23, bb22, bb23);

            const unsigned C0 = packrelu(d0, d1);
            const unsigned C1 = packrelu(d2, d3);
            const unsigned C2 = packrelu(e0, e1);
            const unsigned C3 = packrelu(e2, e3);

            // layer 3: w3 in every column -> z in every D register
            float z0, z1, z2, z3;
            mma16816(z0, z1, z2, z3, C0, C1, C2, C3, b30, b31, 0.f, 0.f, 0.f, 0.f);
            if (t == tq) { zlo = z0; zhi = z2; }

            // advance coords
            xq += 0.125f;
            if (++col == 17) { col = 0; xq = 0.0f; ya += inv128; }
        }

        // ---- epilogue: 2 pixels per thread ----
        {
            const float zv = zlo + b3v;
            float hm = 1.0f / (1.0f + __expf(-zv));
            hm = fminf(fmaxf(hm, EPS_), 1.0f - EPS_);
            float qv = 1.0f - tlo;
            qv = qv * qv; qv = qv * qv;
            negAcc += __logf(1.0f - hm) * hm * hm * qv;
            if (pxlo == posind) {
                const float om = 1.0f - hm;
                atomicAdd(&g_pos_acc, (double)(__logf(hm) * om * om * mval));
            }
        }
        {
            const float zv = zhi + b3v;
            float hm = 1.0f / (1.0f + __expf(-zv));
            hm = fminf(fmaxf(hm, EPS_), 1.0f - EPS_);
            float qv = 1.0f - thi;
            qv = qv * qv; qv = qv * qv;
            negAcc += __logf(1.0f - hm) * hm * hm * qv;
            if (pxlo + 8 == posind) {
                const float om = 1.0f - hm;
                atomicAdd(&g_pos_acc, (double)(__logf(hm) * om * om * mval));
            }
        }
    }

    // ---- block reduction, one double atomic per block ----
    #pragma unroll
    for (int off = 16; off > 0; off >>= 1)
        negAcc += __shfl_down_sync(0xFFFFFFFFu, negAcc, off);
    if (lane == 0) sred[wid] = negAcc;
    __syncthreads();
    if (tid < 32) {
        float v = (tid < 4) ? sred[tid] : 0.0f;
        #pragma unroll
        for (int off = 2; off > 0; off >>= 1)
            v += __shfl_down_sync(0xFFFFFFFFu, v, off);
        if (tid == 0) atomicAdd(&g_neg_acc, (double)v);
    }

    // ---- last-block finalize ----
    if (tid == 0) {
        __threadfence();
        const unsigned c = atomicAdd(&g_done, 1u);
        s_last = (c == TOTALBLK - 1u) ? 1 : 0;
    }
    __syncthreads();
    if (s_last && tid < 32) {
        float np = 0.0f;
        for (int i = tid; i < BM_; i += 32) np += mask[i];
        #pragma unroll
        for (int off = 16; off > 0; off >>= 1)
            np += __shfl_down_sync(0xFFFFFFFFu, np, off);
        if (tid == 0) {
            const double neg = *(volatile double*)&g_neg_acc;
            const double pos = *(volatile double*)&g_pos_acc;
            double loss;
            if (np == 0.0f) loss = -neg;
            else            loss = -(pos + neg) / (double)fmaxf(np, 1.0f);
            out[0] = (float)loss;
        }
    }
}

extern "C" void kernel_launch(void* const* d_in, const int* in_sizes, int n_in,
                              void* d_out, int out_size)
{
    const float* sch_feat    = (const float*)d_in[0];
    const float* conv_weight = (const float*)d_in[1];
    const float* mask        = (const float*)d_in[2];
    const int*   pre_ind     = (const int*)  d_in[3];
    const float* target      = (const float*)d_in[4];
    const int*   ind         = (const int*)  d_in[5];
    float* out = (float*)d_out;

    feat_frag_kernel<<<dim3(NT16 / 4, B_), 128>>>(sch_feat);

    dim3 grid(GRIDX, BM_);
    sch_loss_main<<<grid, 128>>>(conv_weight, mask, pre_ind, target, ind, out);
}

// round 13
// speedup vs baseline: 2.3998x; 1.1999x over previous
#include <cuda_runtime.h>
#include <cuda_fp16.h>
#include <math.h>

// Fixed problem shapes
#define FCN   16
#define WT    593
#define H_    152
#define W_    272
#define HW_   41344
#define B_    4
#define M_    32
#define BM_   128
#define EPS_  1.0e-4f
#define NT16  2584            // HW_/16 pixel tiles
#define NQUAD 646             // groups of 4 tiles (64 px)
#define GRIDX 20
#define TOTALBLK (GRIDX * BM_)

// Scratch (allocations forbidden)
__device__ double   g_neg_acc;
__device__ double   g_pos_acc;
__device__ unsigned g_done;
__device__ uint4    g_featX[(long long)B_ * NT16 * 32];   // fragment-ordered features

__device__ __forceinline__ unsigned pack_h2(float lo, float hi) {
    unsigned d;
    asm("cvt.rn.f16x2.f32 %0, %1, %2;" : "=r"(d) : "f"(hi), "f"(lo));
    return d;
}
__device__ __forceinline__ unsigned relu_h2(unsigned u) {
    __half2 h = *reinterpret_cast<__half2*>(&u);
    h = __hmax2(h, __half2(__float2half_rn(0.f), __float2half_rn(0.f)));
    return *reinterpret_cast<unsigned*>(&h);
}

// ---- pre-pass: build m16k16 A fragments; also resets accumulators ----
__global__ __launch_bounds__(128)
void feat_frag_kernel(const float* __restrict__ sf) {
    if (blockIdx.x == 0 && blockIdx.y == 0 && threadIdx.x == 0) {
        g_neg_acc = 0.0;
        g_pos_acc = 0.0;
        g_done    = 0u;
    }
    __shared__ float sm[4][16][16];   // [w][c][px]
    const int w    = threadIdx.x >> 5;
    const int t    = threadIdx.x & 31;
    const int tile = blockIdx.x * 4 + w;
    const int b    = blockIdx.y;
    const int base = tile * 16;

    const int c  = t >> 1;
    const int h8 = (t & 1) * 8;
    const float* src = sf + ((long long)b * FCN + c) * HW_ + base + h8;
    const float4 v0 = *(const float4*)src;
    const float4 v1 = *(const float4*)(src + 4);
    sm[w][c][h8 + 0] = v0.x; sm[w][c][h8 + 1] = v0.y;
    sm[w][c][h8 + 2] = v0.z; sm[w][c][h8 + 3] = v0.w;
    sm[w][c][h8 + 4] = v1.x; sm[w][c][h8 + 5] = v1.y;
    sm[w][c][h8 + 6] = v1.z; sm[w][c][h8 + 7] = v1.w;
    __syncwarp();

    const int g  = t >> 2;
    const int tq = t & 3;
    const int k0 = 2 * tq, k1 = k0 + 1, k2 = k0 + 8, k3 = k2 + 1;

    __half2 a0 = __floats2half2_rn(sm[w][k0][g],     sm[w][k1][g]);
    __half2 a1 = __floats2half2_rn(sm[w][k0][g + 8], sm[w][k1][g + 8]);
    __half2 a2 = __floats2half2_rn(sm[w][k2][g],     sm[w][k3][g]);
    __half2 a3 = __floats2half2_rn(sm[w][k2][g + 8], sm[w][k3][g + 8]);

    uint4 o;
    o.x = *(unsigned*)&a0; o.y = *(unsigned*)&a1;
    o.z = *(unsigned*)&a2; o.w = *(unsigned*)&a3;
    g_featX[((long long)b * NT16 + tile) * 32 + t] = o;
}

// fp16-output HMMA: D, C are 2x f16x2 regs
__device__ __forceinline__ void mma16816h(
    unsigned& d0, unsigned& d1,
    unsigned a0, unsigned a1, unsigned a2, unsigned a3,
    unsigned b0, unsigned b1,
    unsigned c0, unsigned c1)
{
    asm("mma.sync.aligned.m16n8k16.row.col.f16.f16.f16.f16 "
        "{%0,%1}, {%2,%3,%4,%5}, {%6,%7}, {%8,%9};"
        : "=r"(d0), "=r"(d1)
        : "r"(a0), "r"(a1), "r"(a2), "r"(a3), "r"(b0), "r"(b1),
          "r"(c0), "r"(c1));
}

__global__ __launch_bounds__(128, 6)
void sch_loss_main(const float* __restrict__ conv_weight,
                   const float* __restrict__ mask,
                   const int*   __restrict__ pre_ind,
                   const float* __restrict__ target,
                   const int*   __restrict__ ind,
                   float* __restrict__ out)
{
    __shared__ __align__(4) __half w1h[256];   // [o*16 + c], c<16
    __shared__ __align__(4) __half w2h[256];   // [o*16 + c]
    __shared__ float b1f[16], b2f[16], w3f[16], wxf[16], wyf[16];
    __shared__ float b1c[16];                  // bias with coord offset folded in
    __shared__ float b3s;
    __shared__ float sred[4];
    __shared__ int   s_last;

    const int bm   = blockIdx.y;
    const int b    = bm >> 5;
    const int tid  = threadIdx.x;
    const int wid  = tid >> 5;
    const int lane = tid & 31;
    const int pi   = pre_ind[bm];

    const float x0 = (float)(pi % W_);
    const float y0 = (float)pi / (float)W_;     // float division, matching reference
    const float inv128 = 1.0f / 128.0f;

    // ---- prologue: gather + route 593 weights ----
    for (int idx = tid; idx < WT; idx += 128) {
        const float v = conv_weight[((long long)b * WT + idx) * HW_ + pi];
        if (idx < 288) {
            const int o = idx / 18, c = idx % 18;
            if      (c < 16)  w1h[o * 16 + c] = __float2half_rn(v);
            else if (c == 16) wxf[o] = v;
            else              wyf[o] = v;
        } else if (idx < 304) b1f[idx - 288] = v;
        else if (idx < 560)   w2h[idx - 304] = __float2half_rn(v);
        else if (idx < 576)   b2f[idx - 560] = v;
        else if (idx < 592)   w3f[idx - 576] = v;
        else                  b3s = v;
    }
    __syncthreads();
    if (tid < 16)
        b1c[tid] = b1f[tid] - (wxf[tid] * x0 + wyf[tid] * y0) * inv128;
    __syncthreads();

    const int g  = lane >> 2;
    const int tq = lane & 3;
    const bool tq0 = (tq == 0);
    const int k0 = 2 * tq, k2 = k0 + 8;
    const int k1 = k0 + 1, k3 = k2 + 1;

    const unsigned b1a0 = *(const unsigned*)&w1h[g * 16 + k0];
    const unsigned b1a1 = *(const unsigned*)&w1h[g * 16 + k2];
    const unsigned b1b0 = *(const unsigned*)&w1h[(g + 8) * 16 + k0];
    const unsigned b1b1 = *(const unsigned*)&w1h[(g + 8) * 16 + k2];
    const unsigned b2a0 = *(const unsigned*)&w2h[g * 16 + k0];
    const unsigned b2a1 = *(const unsigned*)&w2h[g * 16 + k2];
    const unsigned b2b0 = *(const unsigned*)&w2h[(g + 8) * 16 + k0];
    const unsigned b2b1 = *(const unsigned*)&w2h[(g + 8) * 16 + k2];
    const unsigned b30 = pack_h2(w3f[k0], w3f[k1]);
    const unsigned b31 = pack_h2(w3f[k2], w3f[k3]);
    const unsigned cbA = tq0 ? pack_h2(wxf[g],     wyf[g])     : 0u;
    const unsigned cbB = tq0 ? pack_h2(wxf[g + 8], wyf[g + 8]) : 0u;

    const unsigned cA1 = pack_h2(b1c[k0], b1c[k1]);
    const unsigned cB1 = pack_h2(b1c[k2], b1c[k3]);
    const unsigned cA2 = pack_h2(b2f[k0], b2f[k1]);
    const unsigned cB2 = pack_h2(b2f[k2], b2f[k3]);
    const float b3v = b3s;

    const float* __restrict__ tg = target + (long long)bm * HW_;
    const char*  __restrict__ fxb = (const char*)(g_featX + (long long)b * NT16 * 32)
                                    + (unsigned)lane * 16u;
    const int   posind = ind[bm];
    const float mval   = mask[bm];
    const float gx = (float)g * inv128;

    float negAcc = 0.0f;

    for (int q = blockIdx.x * 4 + wid; q < NQUAD; q += GRIDX * 4) {
        const int tile0 = q * 4;

        const unsigned off0 = (unsigned)tile0 * 512u;
        const uint4 af0 = *(const uint4*)(fxb + off0);
        const uint4 af1 = *(const uint4*)(fxb + off0 + 512u);
        const uint4 af2 = *(const uint4*)(fxb + off0 + 1024u);
        const uint4 af3 = *(const uint4*)(fxb + off0 + 1536u);
        const int  pxlo = tile0 * 16 + tq * 16 + g;
        const float tlo = tg[pxlo];
        const float thi = tg[pxlo + 8];

        int   col = tile0 % 17;
        float ya  = (float)(tile0 / 17) * inv128;
        float xq  = (float)col * 0.125f;

        unsigned zsel0 = 0u, zsel1 = 0u;

        #pragma unroll
        for (int t = 0; t < 4; ++t) {
            const uint4 af = (t == 0) ? af0 : (t == 1) ? af1 : (t == 2) ? af2 : af3;

            const float xal = xq + gx;
            const unsigned caLo = tq0 ? pack_h2(xal,           ya) : 0u;
            const unsigned caHi = tq0 ? pack_h2(xal + 0.0625f, ya) : 0u;

            unsigned d0, d1, e0, e1;
            mma16816h(d0, d1, af.x, af.y, af.z, af.w, b1a0, b1a1, cA1, cA1);
            mma16816h(e0, e1, af.x, af.y, af.z, af.w, b1b0, b1b1, cB1, cB1);
            mma16816h(d0, d1, caLo, caHi, 0u, 0u, cbA, 0u, d0, d1);
            mma16816h(e0, e1, caLo, caHi, 0u, 0u, cbB, 0u, e0, e1);

            const unsigned A0 = relu_h2(d0);
            const unsigned A1 = relu_h2(d1);
            const unsigned A2 = relu_h2(e0);
            const unsigned A3 = relu_h2(e1);

            mma16816h(d0, d1, A0, A1, A2, A3, b2a0, b2a1, cA2, cA2);
            mma16816h(e0, e1, A0, A1, A2, A3, b2b0, b2b1, cB2, cB2);

            const unsigned C0 = relu_h2(d0);
            const unsigned C1 = relu_h2(d1);
            const unsigned C2 = relu_h2(e0);
            const unsigned C3 = relu_h2(e1);

            unsigned z0, z1;
            mma16816h(z0, z1, C0, C1, C2, C3, b30, b31, 0u, 0u);
            if (t == tq) { zsel0 = z0; zsel1 = z1; }

            xq += 0.125f;
            if (++col == 17) { col = 0; xq = 0.0f; ya += inv128; }
        }

        const __half2 zh0 = *reinterpret_cast<const __half2*>(&zsel0);
        const __half2 zh1 = *reinterpret_cast<const __half2*>(&zsel1);
        const float zvlo = __low2float(zh0);
        const float zvhi = __low2float(zh1);

        {
            const float zv = zvlo + b3v;
            float hm = 1.0f / (1.0f + __expf(-zv));
            hm = fminf(fmaxf(hm, EPS_), 1.0f - EPS_);
            float qv = 1.0f - tlo;
            qv = qv * qv; qv = qv * qv;
            negAcc += __logf(1.0f - hm) * hm * hm * qv;
            if (pxlo == posind) {
                const float om = 1.0f - hm;
                atomicAdd(&g_pos_acc, (double)(__logf(hm) * om * om * mval));
            }
        }
        {
            const float zv = zvhi + b3v;
            float hm = 1.0f / (1.0f + __expf(-zv));
            hm = fminf(fmaxf(hm, EPS_), 1.0f - EPS_);
            float qv = 1.0f - thi;
            qv = qv * qv; qv = qv * qv;
            negAcc += __logf(1.0f - hm) * hm * hm * qv;
            if (pxlo + 8 == posind) {
                const float om = 1.0f - hm;
                atomicAdd(&g_pos_acc, (double)(__logf(hm) * om * om * mval));
            }
        }
    }

    #pragma unroll
    for (int off = 16; off > 0; off >>= 1)
        negAcc += __shfl_down_sync(0xFFFFFFFFu, negAcc, off);
    if (lane == 0) sred[wid] = negAcc;
    __syncthreads();
    if (tid < 32) {
        float v = (tid < 4) ? sred[tid] : 0.0f;
        #pragma unroll
        for (int off = 2; off > 0; off >>= 1)
            v += __shfl_down_sync(0xFFFFFFFFu, v, off);
        if (tid == 0) atomicAdd(&g_neg_acc, (double)v);
    }

    if (tid == 0) {
        __threadfence();
        const unsigned c = atomicAdd(&g_done, 1u);
        s_last = (c == TOTALBLK - 1u) ? 1 : 0;
    }
    __syncthreads();
    if (s_last && tid < 32) {
        float np = 0.0f;
        for (int i = tid; i < BM_; i += 32) np += mask[i];
        #pragma unroll
        for (int off = 16; off > 0; off >>= 1)
            np += __shfl_down_sync(0xFFFFFFFFu, np, off);
        if (tid == 0) {
            const double neg = *(volatile double*)&g_neg_acc;
            const double pos = *(volatile double*)&g_pos_acc;
            double loss;
            if (np == 0.0f) loss = -neg;
            else            loss = -(pos + neg) / (double)fmaxf(np, 1.0f);
            out[0] = (float)loss;
        }
    }
}

extern "C" void kernel_launch(void* const* d_in, const int* in_sizes, int n_in,
                              void* d_out, int out_size)
{
    const float* sch_feat    = (const float*)d_in[0];
    const float* conv_weight = (const float*)d_in[1];
    const float* mask        = (const float*)d_in[2];
    const int*   pre_ind     = (const int*)  d_in[3];
    const float* target      = (const float*)d_in[4];
    const int*   ind         = (const int*)  d_in[5];
    float* out = (float*)d_out;

    feat_frag_kernel<<<dim3(NT16 / 4, B_), 128>>>(sch_feat);

    dim3 grid(GRIDX, BM_);
    sch_loss_main<<<grid, 128>>>(conv_weight, mask, pre_ind, target, ind, out);
}

// round 14
// speedup vs baseline: 2.4819x; 1.0342x over previous
#include <cuda_runtime.h>
#include <cuda_fp16.h>
#include <math.h>

// Fixed problem shapes
#define FCN   16
#define WT    593
#define H_    152
#define W_    272
#define HW_   41344
#define B_    4
#define M_    32
#define BM_   128
#define EPS_  1.0e-4f
#define NT16  2584            // HW_/16 pixel tiles
#define NQUAD 646             // groups of 4 tiles (64 px)
#define GRIDX 20
#define TOTALBLK (GRIDX * BM_)

// Scratch (allocations forbidden)
__device__ double   g_neg_acc;
__device__ double   g_pos_acc;
__device__ unsigned g_done;
__device__ uint4    g_featX[(long long)B_ * NT16 * 32];   // fragment-ordered features
__device__ uint2    g_coordA[NT16 * 32];                  // coord A-fragments (b-independent)

__device__ __forceinline__ unsigned pack_h2(float lo, float hi) {
    unsigned d;
    asm("cvt.rn.f16x2.f32 %0, %1, %2;" : "=r"(d) : "f"(hi), "f"(lo));
    return d;
}
__device__ __forceinline__ unsigned relu_h2(unsigned u) {
    __half2 h = *reinterpret_cast<__half2*>(&u);
    h = __hmax2(h, __half2(__float2half_rn(0.f), __float2half_rn(0.f)));
    return *reinterpret_cast<unsigned*>(&h);
}

// ---- pre-pass: build m16k16 A fragments + coord fragments; resets accumulators ----
__global__ __launch_bounds__(128)
void feat_frag_kernel(const float* __restrict__ sf) {
    if (blockIdx.x == 0 && blockIdx.y == 0 && threadIdx.x == 0) {
        g_neg_acc = 0.0;
        g_pos_acc = 0.0;
        g_done    = 0u;
    }
    __shared__ float sm[4][16][16];   // [w][c][px]
    const int w    = threadIdx.x >> 5;
    const int t    = threadIdx.x & 31;
    const int tile = blockIdx.x * 4 + w;
    const int b    = blockIdx.y;
    const int base = tile * 16;

    const int c  = t >> 1;
    const int h8 = (t & 1) * 8;
    const float* src = sf + ((long long)b * FCN + c) * HW_ + base + h8;
    const float4 v0 = *(const float4*)src;
    const float4 v1 = *(const float4*)(src + 4);
    sm[w][c][h8 + 0] = v0.x; sm[w][c][h8 + 1] = v0.y;
    sm[w][c][h8 + 2] = v0.z; sm[w][c][h8 + 3] = v0.w;
    sm[w][c][h8 + 4] = v1.x; sm[w][c][h8 + 5] = v1.y;
    sm[w][c][h8 + 6] = v1.z; sm[w][c][h8 + 7] = v1.w;
    __syncwarp();

    const int g  = t >> 2;
    const int tq = t & 3;
    const int k0 = 2 * tq, k1 = k0 + 1, k2 = k0 + 8, k3 = k2 + 1;

    __half2 a0 = __floats2half2_rn(sm[w][k0][g],     sm[w][k1][g]);
    __half2 a1 = __floats2half2_rn(sm[w][k0][g + 8], sm[w][k1][g + 8]);
    __half2 a2 = __floats2half2_rn(sm[w][k2][g],     sm[w][k3][g]);
    __half2 a3 = __floats2half2_rn(sm[w][k2][g + 8], sm[w][k3][g + 8]);

    uint4 o;
    o.x = *(unsigned*)&a0; o.y = *(unsigned*)&a1;
    o.z = *(unsigned*)&a2; o.w = *(unsigned*)&a3;
    g_featX[((long long)b * NT16 + tile) * 32 + t] = o;

    // coord A-fragments (tile-dependent only): rows = pixels, k0 = x/128, k1 = y/128.
    // Nonzero only on tq==0 lanes (k=0,1); all values exact in fp16 (ints <= 271 over 2^7).
    if (b == 0) {
        const float inv128 = 1.0f / 128.0f;
        const float xg = (float)((tile % 17) * 16 + g) * inv128;
        const float yv = (float)(tile / 17) * inv128;
        uint2 ca;
        ca.x = (tq == 0) ? pack_h2(xg,                   yv) : 0u;   // row g
        ca.y = (tq == 0) ? pack_h2(xg + 8.0f * inv128,   yv) : 0u;   // row g+8
        g_coordA[tile * 32 + t] = ca;
    }
}

// fp16-output HMMA: D, C are 2x f16x2 regs
__device__ __forceinline__ void mma16816h(
    unsigned& d0, unsigned& d1,
    unsigned a0, unsigned a1, unsigned a2, unsigned a3,
    unsigned b0, unsigned b1,
    unsigned c0, unsigned c1)
{
    asm("mma.sync.aligned.m16n8k16.row.col.f16.f16.f16.f16 "
        "{%0,%1}, {%2,%3,%4,%5}, {%6,%7}, {%8,%9};"
        : "=r"(d0), "=r"(d1)
        : "r"(a0), "r"(a1), "r"(a2), "r"(a3), "r"(b0), "r"(b1),
          "r"(c0), "r"(c1));
}

__global__ __launch_bounds__(128, 6)
void sch_loss_main(const float* __restrict__ conv_weight,
                   const float* __restrict__ mask,
                   const int*   __restrict__ pre_ind,
                   const float* __restrict__ target,
                   const int*   __restrict__ ind,
                   float* __restrict__ out)
{
    __shared__ __align__(4) __half w1h[256];   // [o*16 + c], c<16
    __shared__ __align__(4) __half w2h[256];   // [o*16 + c]
    __shared__ float b1f[16], b2f[16], w3f[16], wxf[16], wyf[16];
    __shared__ float b1c[16];                  // bias with coord offset folded in
    __shared__ float b3s;
    __shared__ float sred[4];
    __shared__ int   s_last;

    const int bm   = blockIdx.y;
    const int b    = bm >> 5;
    const int tid  = threadIdx.x;
    const int wid  = tid >> 5;
    const int lane = tid & 31;
    const int pi   = pre_ind[bm];

    const float x0 = (float)(pi % W_);
    const float y0 = (float)pi / (float)W_;     // float division, matching reference
    const float inv128 = 1.0f / 128.0f;

    // ---- prologue: gather + route 593 weights ----
    for (int idx = tid; idx < WT; idx += 128) {
        const float v = conv_weight[((long long)b * WT + idx) * HW_ + pi];
        if (idx < 288) {
            const int o = idx / 18, c = idx % 18;
            if      (c < 16)  w1h[o * 16 + c] = __float2half_rn(v);
            else if (c == 16) wxf[o] = v;
            else              wyf[o] = v;
        } else if (idx < 304) b1f[idx - 288] = v;
        else if (idx < 560)   w2h[idx - 304] = __float2half_rn(v);
        else if (idx < 576)   b2f[idx - 560] = v;
        else if (idx < 592)   w3f[idx - 576] = v;
        else                  b3s = v;
    }
    __syncthreads();
    if (tid < 16)
        b1c[tid] = b1f[tid] - (wxf[tid] * x0 + wyf[tid] * y0) * inv128;
    __syncthreads();

    const int g  = lane >> 2;
    const int tq = lane & 3;
    const bool tq0 = (tq == 0);
    const int k0 = 2 * tq, k2 = k0 + 8;
    const int k1 = k0 + 1, k3 = k2 + 1;

    const unsigned b1a0 = *(const unsigned*)&w1h[g * 16 + k0];
    const unsigned b1a1 = *(const unsigned*)&w1h[g * 16 + k2];
    const unsigned b1b0 = *(const unsigned*)&w1h[(g + 8) * 16 + k0];
    const unsigned b1b1 = *(const unsigned*)&w1h[(g + 8) * 16 + k2];
    const unsigned b2a0 = *(const unsigned*)&w2h[g * 16 + k0];
    const unsigned b2a1 = *(const unsigned*)&w2h[g * 16 + k2];
    const unsigned b2b0 = *(const unsigned*)&w2h[(g + 8) * 16 + k0];
    const unsigned b2b1 = *(const unsigned*)&w2h[(g + 8) * 16 + k2];
    const unsigned b30 = pack_h2(w3f[k0], w3f[k1]);
    const unsigned b31 = pack_h2(w3f[k2], w3f[k3]);
    const unsigned cbA = tq0 ? pack_h2(wxf[g],     wyf[g])     : 0u;
    const unsigned cbB = tq0 ? pack_h2(wxf[g + 8], wyf[g + 8]) : 0u;

    const unsigned cA1 = pack_h2(b1c[k0], b1c[k1]);
    const unsigned cB1 = pack_h2(b1c[k2], b1c[k3]);
    const unsigned cA2 = pack_h2(b2f[k0], b2f[k1]);
    const unsigned cB2 = pack_h2(b2f[k2], b2f[k3]);
    const float b3v = b3s;

    const float* __restrict__ tg = target + (long long)bm * HW_;
    const char*  __restrict__ fxb = (const char*)(g_featX + (long long)b * NT16 * 32)
                                    + (unsigned)lane * 16u;
    const char*  __restrict__ cab = (const char*)g_coordA + (unsigned)lane * 8u;
    const int   posind = ind[bm];
    const float mval   = mask[bm];

    float negAcc = 0.0f;

    for (int q = blockIdx.x * 4 + wid; q < NQUAD; q += GRIDX * 4) {
        const int tile0 = q * 4;

        // ---- batched independent loads (32-bit offsets; MLP = 10) ----
        const unsigned off0 = (unsigned)tile0 * 512u;
        const uint4 af0 = *(const uint4*)(fxb + off0);
        const uint4 af1 = *(const uint4*)(fxb + off0 + 512u);
        const uint4 af2 = *(const uint4*)(fxb + off0 + 1024u);
        const uint4 af3 = *(const uint4*)(fxb + off0 + 1536u);
        const unsigned coff = (unsigned)tile0 * 256u;
        const uint2 ca0 = *(const uint2*)(cab + coff);
        const uint2 ca1 = *(const uint2*)(cab + coff + 256u);
        const uint2 ca2 = *(const uint2*)(cab + coff + 512u);
        const uint2 ca3 = *(const uint2*)(cab + coff + 768u);
        const int  pxlo = tile0 * 16 + tq * 16 + g;
        const float tlo = tg[pxlo];
        const float thi = tg[pxlo + 8];

        unsigned zsel0 = 0u, zsel1 = 0u;

        #pragma unroll
        for (int t = 0; t < 4; ++t) {
            const uint4 af = (t == 0) ? af0 : (t == 1) ? af1 : (t == 2) ? af2 : af3;
            const uint2 ca = (t == 0) ? ca0 : (t == 1) ? ca1 : (t == 2) ? ca2 : ca3;

            unsigned d0, d1, e0, e1;
            // layer 1 (fp16 out; bias C has coord offset folded) + coord mma
            mma16816h(d0, d1, af.x, af.y, af.z, af.w, b1a0, b1a1, cA1, cA1);
            mma16816h(e0, e1, af.x, af.y, af.z, af.w, b1b0, b1b1, cB1, cB1);
            mma16816h(d0, d1, ca.x, ca.y, 0u, 0u, cbA, 0u, d0, d1);
            mma16816h(e0, e1, ca.x, ca.y, 0u, 0u, cbB, 0u, e0, e1);

            const unsigned A0 = relu_h2(d0);
            const unsigned A1 = relu_h2(d1);
            const unsigned A2 = relu_h2(e0);
            const unsigned A3 = relu_h2(e1);

            // layer 2 (fp16 out)
            mma16816h(d0, d1, A0, A1, A2, A3, b2a0, b2a1, cA2, cA2);
            mma16816h(e0, e1, A0, A1, A2, A3, b2b0, b2b1, cB2, cB2);

            const unsigned C0 = relu_h2(d0);
            const unsigned C1 = relu_h2(d1);
            const unsigned C2 = relu_h2(e0);
            const unsigned C3 = relu_h2(e1);

            // layer 3: w3 broadcast in all columns -> z in every D half
            unsigned z0, z1;
            mma16816h(z0, z1, C0, C1, C2, C3, b30, b31, 0u, 0u);
            if (t == tq) { zsel0 = z0; zsel1 = z1; }
        }

        const __half2 zh0 = *reinterpret_cast<const __half2*>(&zsel0);
        const __half2 zh1 = *reinterpret_cast<const __half2*>(&zsel1);
        const float zvlo = __low2float(zh0);
        const float zvhi = __low2float(zh1);

        // ---- epilogue: 2 pixels per thread ----
        {
            const float zv = zvlo + b3v;
            float hm = 1.0f / (1.0f + __expf(-zv));
            hm = fminf(fmaxf(hm, EPS_), 1.0f - EPS_);
            float qv = 1.0f - tlo;
            qv = qv * qv; qv = qv * qv;
            negAcc += __logf(1.0f - hm) * hm * hm * qv;
            if (pxlo == posind) {
                const float om = 1.0f - hm;
                atomicAdd(&g_pos_acc, (double)(__logf(hm) * om * om * mval));
            }
        }
        {
            const float zv = zvhi + b3v;
            float hm = 1.0f / (1.0f + __expf(-zv));
            hm = fminf(fmaxf(hm, EPS_), 1.0f - EPS_);
            float qv = 1.0f - thi;
            qv = qv * qv; qv = qv * qv;
            negAcc += __logf(1.0f - hm) * hm * hm * qv;
            if (pxlo + 8 == posind) {
                const float om = 1.0f - hm;
                atomicAdd(&g_pos_acc, (double)(__logf(hm) * om * om * mval));
            }
        }
    }

    // ---- block reduction, one double atomic per block ----
    #pragma unroll
    for (int off = 16; off > 0; off >>= 1)
        negAcc += __shfl_down_sync(0xFFFFFFFFu, negAcc, off);
    if (lane == 0) sred[wid] = negAcc;
    __syncthreads();
    if (tid < 32) {
        float v = (tid < 4) ? sred[tid] : 0.0f;
        #pragma unroll
        for (int off = 2; off > 0; off >>= 1)
            v += __shfl_down_sync(0xFFFFFFFFu, v, off);
        if (tid == 0) atomicAdd(&g_neg_acc, (double)v);
    }

    // ---- last-block finalize ----
    if (tid == 0) {
        __threadfence();
        const unsigned c = atomicAdd(&g_done, 1u);
        s_last = (c == TOTALBLK - 1u) ? 1 : 0;
    }
    __syncthreads();
    if (s_last && tid < 32) {
        float np = 0.0f;
        for (int i = tid; i < BM_; i += 32) np += mask[i];
        #pragma unroll
        for (int off = 16; off > 0; off >>= 1)
            np += __shfl_down_sync(0xFFFFFFFFu, np, off);
        if (tid == 0) {
            const double neg = *(volatile double*)&g_neg_acc;
            const double pos = *(volatile double*)&g_pos_acc;
            double loss;
            if (np == 0.0f) loss = -neg;
            else            loss = -(pos + neg) / (double)fmaxf(np, 1.0f);
            out[0] = (float)loss;
        }
    }
}

extern "C" void kernel_launch(void* const* d_in, const int* in_sizes, int n_in,
                              void* d_out, int out_size)
{
    const float* sch_feat    = (const float*)d_in[0];
    const float* conv_weight = (const float*)d_in[1];
    const float* mask        = (const float*)d_in[2];
    const int*   pre_ind     = (const int*)  d_in[3];
    const float* target      = (const float*)d_in[4];
    const int*   ind         = (const int*)  d_in[5];
    float* out = (float*)d_out;

    feat_frag_kernel<<<dim3(NT16 / 4, B_), 128>>>(sch_feat);

    dim3 grid(GRIDX, BM_);
    sch_loss_main<<<grid, 128>>>(conv_weight, mask, pre_ind, target, ind, out);
}

// round 15
// speedup vs baseline: 2.5648x; 1.0334x over previous
#include <cuda_runtime.h>
#include <cuda_fp16.h>
#include <math.h>

// Fixed problem shapes
#define FCN   16
#define WT    593
#define H_    152
#define W_    272
#define HW_   41344
#define B_    4
#define M_    32
#define BM_   128
#define EPS_  1.0e-4f
#define NT16  2584            // HW_/16 pixel tiles
#define NQUAD 646             // groups of 4 tiles (64 px)
#define GRIDX 20
#define TOTALBLK (GRIDX * BM_)

// Scratch (allocations forbidden)
__device__ double   g_neg_acc;
__device__ double   g_pos_acc;
__device__ unsigned g_done;
__device__ uint4    g_featX[(long long)B_ * NT16 * 32];   // fragment-ordered features
__device__ uint2    g_coordA[NT16 * 32];                  // per-lane packed (x/128, y/128)

__device__ __forceinline__ unsigned pack_h2(float lo, float hi) {
    unsigned d;
    asm("cvt.rn.f16x2.f32 %0, %1, %2;" : "=r"(d) : "f"(hi), "f"(lo));
    return d;
}
__device__ __forceinline__ unsigned relu_h2(unsigned u) {
    __half2 h = *reinterpret_cast<__half2*>(&u);
    h = __hmax2(h, __half2(__float2half_rn(0.f), __float2half_rn(0.f)));
    return *reinterpret_cast<unsigned*>(&h);
}
__device__ __forceinline__ __half2 asH2(unsigned u) {
    return *reinterpret_cast<const __half2*>(&u);
}
__device__ __forceinline__ unsigned asU(__half2 h) {
    return *reinterpret_cast<const unsigned*>(&h);
}

// ---- pre-pass: build m16k16 A fragments + coord pairs; resets accumulators ----
__global__ __launch_bounds__(128)
void feat_frag_kernel(const float* __restrict__ sf) {
    if (blockIdx.x == 0 && blockIdx.y == 0 && threadIdx.x == 0) {
        g_neg_acc = 0.0;
        g_pos_acc = 0.0;
        g_done    = 0u;
    }
    __shared__ float sm[4][16][16];   // [w][c][px]
    const int w    = threadIdx.x >> 5;
    const int t    = threadIdx.x & 31;
    const int tile = blockIdx.x * 4 + w;
    const int b    = blockIdx.y;
    const int base = tile * 16;

    const int c  = t >> 1;
    const int h8 = (t & 1) * 8;
    const float* src = sf + ((long long)b * FCN + c) * HW_ + base + h8;
    const float4 v0 = *(const float4*)src;
    const float4 v1 = *(const float4*)(src + 4);
    sm[w][c][h8 + 0] = v0.x; sm[w][c][h8 + 1] = v0.y;
    sm[w][c][h8 + 2] = v0.z; sm[w][c][h8 + 3] = v0.w;
    sm[w][c][h8 + 4] = v1.x; sm[w][c][h8 + 5] = v1.y;
    sm[w][c][h8 + 6] = v1.z; sm[w][c][h8 + 7] = v1.w;
    __syncwarp();

    const int g  = t >> 2;
    const int tq = t & 3;
    const int k0 = 2 * tq, k1 = k0 + 1, k2 = k0 + 8, k3 = k2 + 1;

    __half2 a0 = __floats2half2_rn(sm[w][k0][g],     sm[w][k1][g]);
    __half2 a1 = __floats2half2_rn(sm[w][k0][g + 8], sm[w][k1][g + 8]);
    __half2 a2 = __floats2half2_rn(sm[w][k2][g],     sm[w][k3][g]);
    __half2 a3 = __floats2half2_rn(sm[w][k2][g + 8], sm[w][k3][g + 8]);

    uint4 o;
    o.x = *(unsigned*)&a0; o.y = *(unsigned*)&a1;
    o.z = *(unsigned*)&a2; o.w = *(unsigned*)&a3;
    g_featX[((long long)b * NT16 + tile) * 32 + t] = o;

    // per-lane coord pack: (x_row/128, y/128) for rows g and g+8.
    // All values exact in fp16 (ints <= 271 over 2^7). Stored for EVERY lane.
    if (b == 0) {
        const float inv128 = 1.0f / 128.0f;
        const float xg = (float)((tile % 17) * 16 + g) * inv128;
        const float yv = (float)(tile / 17) * inv128;
        uint2 ca;
        ca.x = pack_h2(xg,                 yv);   // row g
        ca.y = pack_h2(xg + 8.0f * inv128, yv);   // row g+8
        g_coordA[tile * 32 + t] = ca;
    }
}

// fp16-output HMMA: D, C are 2x f16x2 regs
__device__ __forceinline__ void mma16816h(
    unsigned& d0, unsigned& d1,
    unsigned a0, unsigned a1, unsigned a2, unsigned a3,
    unsigned b0, unsigned b1,
    unsigned c0, unsigned c1)
{
    asm("mma.sync.aligned.m16n8k16.row.col.f16.f16.f16.f16 "
        "{%0,%1}, {%2,%3,%4,%5}, {%6,%7}, {%8,%9};"
        : "=r"(d0), "=r"(d1)
        : "r"(a0), "r"(a1), "r"(a2), "r"(a3), "r"(b0), "r"(b1),
          "r"(c0), "r"(c1));
}

__global__ __launch_bounds__(128, 6)
void sch_loss_main(const float* __restrict__ conv_weight,
                   const float* __restrict__ mask,
                   const int*   __restrict__ pre_ind,
                   const float* __restrict__ target,
                   const int*   __restrict__ ind,
                   float* __restrict__ out)
{
    __shared__ __align__(4) __half w1h[256];   // [o*16 + c], c<16
    __shared__ __align__(4) __half w2h[256];   // [o*16 + c]
    __shared__ float b1f[16], b2f[16], w3f[16], wxf[16], wyf[16];
    __shared__ float b1c[16];                  // bias with coord offset folded in
    __shared__ float b3s;
    __shared__ float sred[4];
    __shared__ int   s_last;

    const int bm   = blockIdx.y;
    const int b    = bm >> 5;
    const int tid  = threadIdx.x;
    const int wid  = tid >> 5;
    const int lane = tid & 31;
    const int pi   = pre_ind[bm];

    const float x0 = (float)(pi % W_);
    const float y0 = (float)pi / (float)W_;     // float division, matching reference
    const float inv128 = 1.0f / 128.0f;

    // ---- prologue: gather + route 593 weights ----
    for (int idx = tid; idx < WT; idx += 128) {
        const float v = conv_weight[((long long)b * WT + idx) * HW_ + pi];
        if (idx < 288) {
            const int o = idx / 18, c = idx % 18;
            if      (c < 16)  w1h[o * 16 + c] = __float2half_rn(v);
            else if (c == 16) wxf[o] = v;
            else              wyf[o] = v;
        } else if (idx < 304) b1f[idx - 288] = v;
        else if (idx < 560)   w2h[idx - 304] = __float2half_rn(v);
        else if (idx < 576)   b2f[idx - 560] = v;
        else if (idx < 592)   w3f[idx - 576] = v;
        else                  b3s = v;
    }
    __syncthreads();
    if (tid < 16)
        b1c[tid] = b1f[tid] - (wxf[tid] * x0 + wyf[tid] * y0) * inv128;
    __syncthreads();

    const int g  = lane >> 2;
    const int tq = lane & 3;
    const int k0 = 2 * tq, k2 = k0 + 8;
    const int k1 = k0 + 1, k3 = k2 + 1;

    const unsigned b1a0 = *(const unsigned*)&w1h[g * 16 + k0];
    const unsigned b1a1 = *(const unsigned*)&w1h[g * 16 + k2];
    const unsigned b1b0 = *(const unsigned*)&w1h[(g + 8) * 16 + k0];
    const unsigned b1b1 = *(const unsigned*)&w1h[(g + 8) * 16 + k2];
    const unsigned b2a0 = *(const unsigned*)&w2h[g * 16 + k0];
    const unsigned b2a1 = *(const unsigned*)&w2h[g * 16 + k2];
    const unsigned b2b0 = *(const unsigned*)&w2h[(g + 8) * 16 + k0];
    const unsigned b2b1 = *(const unsigned*)&w2h[(g + 8) * 16 + k2];
    const unsigned b30 = pack_h2(w3f[k0], w3f[k1]);
    const unsigned b31 = pack_h2(w3f[k2], w3f[k3]);

    // coord weights at this thread's D columns (for C-operand FMA)
    const __half2 cwx01 = asH2(pack_h2(wxf[k0], wxf[k1]));
    const __half2 cwx23 = asH2(pack_h2(wxf[k2], wxf[k3]));
    const __half2 cwy01 = asH2(pack_h2(wyf[k0], wyf[k1]));
    const __half2 cwy23 = asH2(pack_h2(wyf[k2], wyf[k3]));

    const __half2 cA1 = asH2(pack_h2(b1c[k0], b1c[k1]));
    const __half2 cB1 = asH2(pack_h2(b1c[k2], b1c[k3]));
    const unsigned cA2 = pack_h2(b2f[k0], b2f[k1]);
    const unsigned cB2 = pack_h2(b2f[k2], b2f[k3]);
    const float b3v = b3s;

    const float* __restrict__ tg = target + (long long)bm * HW_;
    const char*  __restrict__ fxb = (const char*)(g_featX + (long long)b * NT16 * 32)
                                    + (unsigned)lane * 16u;
    const char*  __restrict__ cab = (const char*)g_coordA + (unsigned)lane * 8u;
    const int   posind = ind[bm];
    const float mval   = mask[bm];

    float negAcc = 0.0f;

    for (int q = blockIdx.x * 4 + wid; q < NQUAD; q += GRIDX * 4) {
        const int tile0 = q * 4;

        // ---- batched independent loads (32-bit offsets; MLP = 10) ----
        const unsigned off0 = (unsigned)tile0 * 512u;
        const uint4 af0 = *(const uint4*)(fxb + off0);
        const uint4 af1 = *(const uint4*)(fxb + off0 + 512u);
        const uint4 af2 = *(const uint4*)(fxb + off0 + 1024u);
        const uint4 af3 = *(const uint4*)(fxb + off0 + 1536u);
        const unsigned coff = (unsigned)tile0 * 256u;
        const uint2 ca0 = *(const uint2*)(cab + coff);
        const uint2 ca1 = *(const uint2*)(cab + coff + 256u);
        const uint2 ca2 = *(const uint2*)(cab + coff + 512u);
        const uint2 ca3 = *(const uint2*)(cab + coff + 768u);
        const int  pxlo = tile0 * 16 + tq * 16 + g;
        const float tlo = tg[pxlo];
        const float thi = tg[pxlo + 8];

        unsigned zsel0 = 0u, zsel1 = 0u;

        #pragma unroll
        for (int t = 0; t < 4; ++t) {
            const uint4 af = (t == 0) ? af0 : (t == 1) ? af1 : (t == 2) ? af2 : af3;
            const uint2 ca = (t == 0) ? ca0 : (t == 1) ? ca1 : (t == 2) ? ca2 : ca3;

            // C-operand coord fold: C(r,n) = b1c_n + wx_n*x_r/128 + wy_n*y/128
            // (identical math to the old coord-mma, computed OFF the mma chain)
            const __half2 cahx = asH2(ca.x);             // (x_g/128, y/128)
            const __half2 cbhx = asH2(ca.y);             // (x_g8/128, y/128)
            const __half2 hxg  = __low2half2(cahx);
            const __half2 hxg8 = __low2half2(cbhx);
            const __half2 hy   = __high2half2(cahx);
            const __half2 ty01 = __hfma2(cwy01, hy, cA1);
            const __half2 ty23 = __hfma2(cwy23, hy, cB1);
            const unsigned cd0 = asU(__hfma2(cwx01, hxg,  ty01));
            const unsigned cd1 = asU(__hfma2(cwx01, hxg8, ty01));
            const unsigned ce0 = asU(__hfma2(cwx23, hxg,  ty23));
            const unsigned ce1 = asU(__hfma2(cwx23, hxg8, ty23));

            unsigned d0, d1, e0, e1;
            // layer 1 (fp16 out), coord+bias carried in C — no coord mma
            mma16816h(d0, d1, af.x, af.y, af.z, af.w, b1a0, b1a1, cd0, cd1);
            mma16816h(e0, e1, af.x, af.y, af.z, af.w, b1b0, b1b1, ce0, ce1);

            const unsigned A0 = relu_h2(d0);
            const unsigned A1 = relu_h2(d1);
            const unsigned A2 = relu_h2(e0);
            const unsigned A3 = relu_h2(e1);

            // layer 2 (fp16 out)
            mma16816h(d0, d1, A0, A1, A2, A3, b2a0, b2a1, cA2, cA2);
            mma16816h(e0, e1, A0, A1, A2, A3, b2b0, b2b1, cB2, cB2);

            const unsigned C0 = relu_h2(d0);
            const unsigned C1 = relu_h2(d1);
            const unsigned C2 = relu_h2(e0);
            const unsigned C3 = relu_h2(e1);

            // layer 3: w3 broadcast in all columns -> z in every D half
            unsigned z0, z1;
            mma16816h(z0, z1, C0, C1, C2, C3, b30, b31, 0u, 0u);
            if (t == tq) { zsel0 = z0; zsel1 = z1; }
        }

        const __half2 zh0 = asH2(zsel0);
        const __half2 zh1 = asH2(zsel1);
        const float zvlo = __low2float(zh0);
        const float zvhi = __low2float(zh1);

        // ---- epilogue: 2 pixels per thread ----
        {
            const float zv = zvlo + b3v;
            float hm = 1.0f / (1.0f + __expf(-zv));
            hm = fminf(fmaxf(hm, EPS_), 1.0f - EPS_);
            float qv = 1.0f - tlo;
            qv = qv * qv; qv = qv * qv;
            negAcc += __logf(1.0f - hm) * hm * hm * qv;
            if (pxlo == posind) {
                const float om = 1.0f - hm;
                atomicAdd(&g_pos_acc, (double)(__logf(hm) * om * om * mval));
            }
        }
        {
            const float zv = zvhi + b3v;
            float hm = 1.0f / (1.0f + __expf(-zv));
            hm = fminf(fmaxf(hm, EPS_), 1.0f - EPS_);
            float qv = 1.0f - thi;
            qv = qv * qv; qv = qv * qv;
            negAcc += __logf(1.0f - hm) * hm * hm * qv;
            if (pxlo + 8 == posind) {
                const float om = 1.0f - hm;
                atomicAdd(&g_pos_acc, (double)(__logf(hm) * om * om * mval));
            }
        }
    }

    // ---- block reduction, one double atomic per block ----
    #pragma unroll
    for (int off = 16; off > 0; off >>= 1)
        negAcc += __shfl_down_sync(0xFFFFFFFFu, negAcc, off);
    if (lane == 0) sred[wid] = negAcc;
    __syncthreads();
    if (tid < 32) {
        float v = (tid < 4) ? sred[tid] : 0.0f;
        #pragma unroll
        for (int off = 2; off > 0; off >>= 1)
            v += __shfl_down_sync(0xFFFFFFFFu, v, off);
        if (tid == 0) atomicAdd(&g_neg_acc, (double)v);
    }

    // ---- last-block finalize ----
    if (tid == 0) {
        __threadfence();
        const unsigned c = atomicAdd(&g_done, 1u);
        s_last = (c == TOTALBLK - 1u) ? 1 : 0;
    }
    __syncthreads();
    if (s_last && tid < 32) {
        float np = 0.0f;
        for (int i = tid; i < BM_; i += 32) np += mask[i];
        #pragma unroll
        for (int off = 16; off > 0; off >>= 1)
            np += __shfl_down_sync(0xFFFFFFFFu, np, off);
        if (tid == 0) {
            const double neg = *(volatile double*)&g_neg_acc;
            const double pos = *(volatile double*)&g_pos_acc;
            double loss;
            if (np == 0.0f) loss = -neg;
            else            loss = -(pos + neg) / (double)fmaxf(np, 1.0f);
            out[0] = (float)loss;
        }
    }
}

extern "C" void kernel_launch(void* const* d_in, const int* in_sizes, int n_in,
                              void* d_out, int out_size)
{
    const float* sch_feat    = (const float*)d_in[0];
    const float* conv_weight = (const float*)d_in[1];
    const float* mask        = (const float*)d_in[2];
    const int*   pre_ind     = (const int*)  d_in[3];
    const float* target      = (const float*)d_in[4];
    const int*   ind         = (const int*)  d_in[5];
    float* out = (float*)d_out;

    feat_frag_kernel<<<dim3(NT16 / 4, B_), 128>>>(sch_feat);

    dim3 grid(GRIDX, BM_);
    sch_loss_main<<<grid, 128>>>(conv_weight, mask, pre_ind, target, ind, out);
}